// round 8
// baseline (speedup 1.0000x reference)
#include <cuda_runtime.h>
#include <cuda_bf16.h>
#include <cstdint>

// Fused per-variable MLP on mma.sync m16n8k16 bf16, hi/lo 3-pass split.
// R8: R7 (ldmatrix.x4 frag loads, half-CTA named barriers) + race fix:
// H1 fp32 scratch gets a per-half window inside the dead X region so one
// half's layer-1 epilogue can never clobber the other half's live X rows.

#define DD 128
#define HH 64
#define OO 2
#define BT 64
#define NT 256
#define SLOPE 0.01f
#define BATCH 8192

// row strides in BYTES
#define XS   272
#define W0S  272
#define W1S  144
#define HS   144

#define XT_BYTES  (BT*XS)
#define W0T_BYTES (HH*W0S)
#define W1T_BYTES (HH*W1S)

__device__ __align__(16) unsigned char gXhi[BATCH*XS];
__device__ __align__(16) unsigned char gXlo[BATCH*XS];
__device__ __align__(16) unsigned char gW0hi[DD*W0T_BYTES];
__device__ __align__(16) unsigned char gW0lo[DD*W0T_BYTES];
__device__ __align__(16) unsigned char gW1hi[DD*W1T_BYTES];
__device__ __align__(16) unsigned char gW1lo[DD*W1T_BYTES];

// smem byte offsets
#define SM_XHI  0
#define SM_XLO  17408
#define SM_W0HI 34816
#define SM_W0LO 52224
#define SM_W1HI 69632
#define SM_W1LO 78848
#define SM_HHI  88064
#define SM_HLO  97280
#define SM_H1   0         // alias XHI; per-half windows via H1OFF
#define SM_B0   106496
#define SM_B1   106752
#define SM_W2   107008
#define SMEM_BYTES 107520

// per-half H1 window: half h rows live inside half h's own X rows
// row r -> (r>>5)*8704 + (r&31)*264 bytes  (264B = 66 f32 stride)
#define H1OFF(r) (((r) >> 5) * 8704 + ((r) & 31) * 264)

static __device__ __forceinline__ void mma_bf16(float acc[4], const uint32_t a[4],
                                                uint32_t b0, uint32_t b1) {
    asm volatile(
        "mma.sync.aligned.m16n8k16.row.col.f32.bf16.bf16.f32 "
        "{%0,%1,%2,%3}, {%4,%5,%6,%7}, {%8,%9}, {%0,%1,%2,%3};"
        : "+f"(acc[0]), "+f"(acc[1]), "+f"(acc[2]), "+f"(acc[3])
        : "r"(a[0]), "r"(a[1]), "r"(a[2]), "r"(a[3]), "r"(b0), "r"(b1));
}
#define LDM4(d0, d1, d2, d3, a) asm volatile( \
    "ldmatrix.sync.aligned.m8n8.x4.shared.b16 {%0,%1,%2,%3}, [%4];" \
    : "=r"(d0), "=r"(d1), "=r"(d2), "=r"(d3) : "r"(a))

static __device__ __forceinline__ void split2(float a, float b, uint32_t& hi, uint32_t& lo) {
    __nv_bfloat16 ah = __float2bfloat16(a), bh = __float2bfloat16(b);
    __nv_bfloat16 al = __float2bfloat16(a - __bfloat162float(ah));
    __nv_bfloat16 bl = __float2bfloat16(b - __bfloat162float(bh));
    __nv_bfloat162 h2 = __halves2bfloat162(ah, bh), l2 = __halves2bfloat162(al, bl);
    hi = *reinterpret_cast<uint32_t*>(&h2);
    lo = *reinterpret_cast<uint32_t*>(&l2);
}
static __device__ __forceinline__ void split1(float a, __nv_bfloat16& h, __nv_bfloat16& l) {
    h = __float2bfloat16(a);
    l = __float2bfloat16(a - __bfloat162float(h));
}
#define CP16(sdst, gsrc) asm volatile( \
    "cp.async.cg.shared.global [%0], [%1], 16;" :: "r"(sdst), "l"(gsrc))

// ===================== prep =====================
#define NX4  (BATCH*DD/4)
#define NW04 (DD*HH*DD/4)
#define NW14 (DD*HH*HH/4)

__global__ void __launch_bounds__(256)
prep_kernel(const float* __restrict__ x, const float* __restrict__ w0,
            const float* __restrict__ w1)
{
    int idx = blockIdx.x * 256 + threadIdx.x;
    if (idx < NX4) {
        int r = idx >> 5, c = idx & 31;
        float4 v = reinterpret_cast<const float4*>(x)[idx];
        uint32_t h0, l0, h1, l1;
        split2(v.x, v.y, h0, l0); split2(v.z, v.w, h1, l1);
        *reinterpret_cast<uint2*>(gXhi + r * XS + c * 8) = make_uint2(h0, h1);
        *reinterpret_cast<uint2*>(gXlo + r * XS + c * 8) = make_uint2(l0, l1);
    } else if (idx < NX4 + NW04) {
        int j = idx - NX4;
        int t = j >> 11, k = j & 2047;
        int i = k >> 5, c4 = k & 31;
        float4 v = reinterpret_cast<const float4*>(w0)[j];
        if (c4 == (t >> 2)) reinterpret_cast<float*>(&v)[t & 3] = 0.0f;
        uint32_t h0, l0, h1, l1;
        split2(v.x, v.y, h0, l0); split2(v.z, v.w, h1, l1);
        *reinterpret_cast<uint2*>(gW0hi + t * W0T_BYTES + i * W0S + c4 * 8) = make_uint2(h0, h1);
        *reinterpret_cast<uint2*>(gW0lo + t * W0T_BYTES + i * W0S + c4 * 8) = make_uint2(l0, l1);
    } else if (idx < NX4 + NW04 + NW14) {
        int j = idx - NX4 - NW04;
        int t = j >> 10, k = j & 1023;
        int i = k >> 4, c4 = k & 15;
        float4 v = reinterpret_cast<const float4*>(w1)[j];
        uint32_t h0, l0, h1, l1;
        split2(v.x, v.y, h0, l0); split2(v.z, v.w, h1, l1);
        *reinterpret_cast<uint2*>(gW1hi + t * W1T_BYTES + i * W1S + c4 * 8) = make_uint2(h0, h1);
        *reinterpret_cast<uint2*>(gW1lo + t * W1T_BYTES + i * W1S + c4 * 8) = make_uint2(l0, l1);
    }
}

// ===================== main =====================
__global__ void __launch_bounds__(NT, 2)
fused_mlp_hmma(const float* __restrict__ w2, const float* __restrict__ b0,
               const float* __restrict__ b1, const float* __restrict__ b2,
               float* __restrict__ out)
{
    extern __shared__ char smem[];
    const int t = blockIdx.x, brow0 = blockIdx.y * BT;
    const int tid = threadIdx.x, wid = tid >> 5, lid = tid & 31;
    const int gid = lid >> 2, tid4 = lid & 3;
    const int m0 = (wid & 3) * 16;
    const int rbB = (wid >> 2) * 32;
    const int barid = 1 + (wid >> 2);          // named barrier per batch half
    const int mat = lid >> 3, r8 = lid & 7;    // ldmatrix lane roles

    uint32_t sb;
    asm("{ .reg .u64 tt; cvta.to.shared.u64 tt, %1; cvt.u32.u64 %0, tt; }"
        : "=r"(sb) : "l"(smem));

    // ---- staging: contiguous cp.async ----
    {
        const unsigned char* xh = gXhi + (size_t)brow0 * XS;
        const unsigned char* xl = gXlo + (size_t)brow0 * XS;
        const unsigned char* w0h = gW0hi + (size_t)t * W0T_BYTES;
        const unsigned char* w0l = gW0lo + (size_t)t * W0T_BYTES;
        const unsigned char* w1h = gW1hi + (size_t)t * W1T_BYTES;
        const unsigned char* w1l = gW1lo + (size_t)t * W1T_BYTES;
        #pragma unroll
        for (int i = tid; i < XT_BYTES / 16; i += NT) {
            CP16(sb + SM_XHI + i * 16, xh + i * 16);
            CP16(sb + SM_XLO + i * 16, xl + i * 16);
            CP16(sb + SM_W0HI + i * 16, w0h + i * 16);
            CP16(sb + SM_W0LO + i * 16, w0l + i * 16);
        }
        #pragma unroll
        for (int i = tid; i < W1T_BYTES / 16; i += NT) {
            CP16(sb + SM_W1HI + i * 16, w1h + i * 16);
            CP16(sb + SM_W1LO + i * 16, w1l + i * 16);
        }
        asm volatile("cp.async.commit_group;" ::: "memory");
    }
    if (tid < HH) {
        reinterpret_cast<float*>(smem + SM_B0)[tid] = b0[t * HH + tid];
        reinterpret_cast<float*>(smem + SM_B1)[tid] = b1[t * HH + tid];
    }
    if (tid < OO * HH)
        reinterpret_cast<float*>(smem + SM_W2)[tid] = w2[(size_t)t * OO * HH + tid];
    asm volatile("cp.async.wait_group 0;" ::: "memory");
    __syncthreads();   // last full-CTA barrier; halves independent hereafter

    uint32_t wh[8][4], wl[8][4];

    // ============================ LAYER 0 ============================
    {
        const uint32_t aHb = sb + SM_W0HI + (m0 + (mat & 1) * 8 + r8) * W0S + (mat >> 1) * 16;
        const uint32_t aLb = sb + SM_W0LO + (m0 + (mat & 1) * 8 + r8) * W0S + (mat >> 1) * 16;
        #pragma unroll
        for (int ks = 0; ks < 8; ks++) {
            LDM4(wh[ks][0], wh[ks][1], wh[ks][2], wh[ks][3], aHb + ks * 32);
            LDM4(wl[ks][0], wl[ks][1], wl[ks][2], wl[ks][3], aLb + ks * 32);
        }
        const uint32_t bBase = sb + ((mat >= 2) ? SM_XLO : SM_XHI)
                             + (rbB + r8) * XS + (mat & 1) * 16;
        const float bA = reinterpret_cast<const float*>(smem + SM_B0)[m0 + gid];
        const float bB = reinterpret_cast<const float*>(smem + SM_B0)[m0 + gid + 8];
        #pragma unroll
        for (int nt = 0; nt < 4; nt++) {
            const int rb = rbB + nt * 8;
            const uint32_t bnt = bBase + nt * 8 * XS;
            float a0[4] = {0.f,0.f,0.f,0.f}, a1[4] = {0.f,0.f,0.f,0.f}, a2[4] = {0.f,0.f,0.f,0.f};
            #pragma unroll
            for (int ks = 0; ks < 8; ks++) {
                uint32_t bh0, bh1, bl0, bl1;
                LDM4(bh0, bh1, bl0, bl1, bnt + ks * 32);
                mma_bf16(a0, wh[ks], bh0, bh1);
                mma_bf16(a1, wh[ks], bl0, bl1);
                mma_bf16(a2, wl[ks], bh0, bh1);
            }
            const int R0 = rb + 2 * tid4, I0 = m0 + gid;
            float v0 = a0[0] + a1[0] + a2[0] + bA;
            float v1 = a0[1] + a1[1] + a2[1] + bA;
            float v2 = a0[2] + a1[2] + a2[2] + bB;
            float v3 = a0[3] + a1[3] + a2[3] + bB;
            v0 = (v0 > 0.f) ? v0 : SLOPE * v0;
            v1 = (v1 > 0.f) ? v1 : SLOPE * v1;
            v2 = (v2 > 0.f) ? v2 : SLOPE * v2;
            v3 = (v3 > 0.f) ? v3 : SLOPE * v3;
            __nv_bfloat16 h, l;
            char* Hh = smem + SM_HHI; char* Hl = smem + SM_HLO;
            split1(v0, h, l);
            *reinterpret_cast<__nv_bfloat16*>(Hh + R0 * HS + I0 * 2) = h;
            *reinterpret_cast<__nv_bfloat16*>(Hl + R0 * HS + I0 * 2) = l;
            split1(v1, h, l);
            *reinterpret_cast<__nv_bfloat16*>(Hh + (R0 + 1) * HS + I0 * 2) = h;
            *reinterpret_cast<__nv_bfloat16*>(Hl + (R0 + 1) * HS + I0 * 2) = l;
            split1(v2, h, l);
            *reinterpret_cast<__nv_bfloat16*>(Hh + R0 * HS + (I0 + 8) * 2) = h;
            *reinterpret_cast<__nv_bfloat16*>(Hl + R0 * HS + (I0 + 8) * 2) = l;
            split1(v3, h, l);
            *reinterpret_cast<__nv_bfloat16*>(Hh + (R0 + 1) * HS + (I0 + 8) * 2) = h;
            *reinterpret_cast<__nv_bfloat16*>(Hl + (R0 + 1) * HS + (I0 + 8) * 2) = l;
        }
    }
    asm volatile("bar.sync %0, 128;" :: "r"(barid) : "memory");

    // ============================ LAYER 1 ============================
    {
        const uint32_t aHb = sb + SM_W1HI + (m0 + (mat & 1) * 8 + r8) * W1S + (mat >> 1) * 16;
        const uint32_t aLb = sb + SM_W1LO + (m0 + (mat & 1) * 8 + r8) * W1S + (mat >> 1) * 16;
        #pragma unroll
        for (int ks = 0; ks < 4; ks++) {
            LDM4(wh[ks][0], wh[ks][1], wh[ks][2], wh[ks][3], aHb + ks * 32);
            LDM4(wl[ks][0], wl[ks][1], wl[ks][2], wl[ks][3], aLb + ks * 32);
        }
        const uint32_t bBase = sb + ((mat >= 2) ? SM_HLO : SM_HHI)
                             + (rbB + r8) * HS + (mat & 1) * 16;
        const float bA = reinterpret_cast<const float*>(smem + SM_B1)[m0 + gid];
        const float bB = reinterpret_cast<const float*>(smem + SM_B1)[m0 + gid + 8];
        #pragma unroll
        for (int nt = 0; nt < 4; nt++) {
            const int rb = rbB + nt * 8;
            const uint32_t bnt = bBase + nt * 8 * HS;
            float a0[4] = {0.f,0.f,0.f,0.f}, a1[4] = {0.f,0.f,0.f,0.f}, a2[4] = {0.f,0.f,0.f,0.f};
            #pragma unroll
            for (int ks = 0; ks < 4; ks++) {
                uint32_t bh0, bh1, bl0, bl1;
                LDM4(bh0, bh1, bl0, bl1, bnt + ks * 32);
                mma_bf16(a0, wh[ks], bh0, bh1);
                mma_bf16(a1, wh[ks], bl0, bl1);
                mma_bf16(a2, wl[ks], bh0, bh1);
            }
            const int R0 = rb + 2 * tid4, I0 = m0 + gid;
            float v0 = a0[0] + a1[0] + a2[0] + bA;
            float v1 = a0[1] + a1[1] + a2[1] + bA;
            float v2 = a0[2] + a1[2] + a2[2] + bB;
            float v3 = a0[3] + a1[3] + a2[3] + bB;
            v0 = (v0 > 0.f) ? v0 : SLOPE * v0;
            v1 = (v1 > 0.f) ? v1 : SLOPE * v1;
            v2 = (v2 > 0.f) ? v2 : SLOPE * v2;
            v3 = (v3 > 0.f) ? v3 : SLOPE * v3;
            // per-half H1 window (race-free aliasing over own X rows)
            float* H1a = reinterpret_cast<float*>(smem + SM_H1 + H1OFF(R0));
            float* H1b = reinterpret_cast<float*>(smem + SM_H1 + H1OFF(R0 + 1));
            H1a[I0]     = v0;
            H1b[I0]     = v1;
            H1a[I0 + 8] = v2;
            H1b[I0 + 8] = v3;
        }
    }
    asm volatile("bar.sync %0, 128;" :: "r"(barid) : "memory");

    // ================= LAYER 2: 256 threads, k split + shfl =================
    {
        const int row = tid >> 2;              // 0..63, stays within own half
        const int o   = (tid >> 1) & 1;
        const int kh  = tid & 1;
        const float* H1 = reinterpret_cast<const float*>(smem + SM_H1 + H1OFF(row)) + kh * 32;
        const float* W2 = reinterpret_cast<const float*>(smem + SM_W2) + o * HH + kh * 32;
        float acc = kh ? 0.0f : b2[t * OO + o];
        #pragma unroll
        for (int k = 0; k < 32; k++) acc = fmaf(H1[k], W2[k], acc);
        acc += __shfl_xor_sync(0xffffffffu, acc, 1);
        if (kh == 0)
            out[(size_t)(brow0 + row) * (DD * OO) + t * OO + o] = acc;
    }
}

extern "C" void kernel_launch(void* const* d_in, const int* in_sizes, int n_in,
                              void* d_out, int out_size)
{
    const float* x  = (const float*)d_in[0];
    const float* w0 = (const float*)d_in[1];
    const float* w1 = (const float*)d_in[2];
    const float* w2 = (const float*)d_in[3];
    const float* b0 = (const float*)d_in[4];
    const float* b1 = (const float*)d_in[5];
    const float* b2 = (const float*)d_in[6];
    float* out = (float*)d_out;

    const int B = in_sizes[0] / DD;

    cudaFuncSetAttribute(fused_mlp_hmma,
                         cudaFuncAttributeMaxDynamicSharedMemorySize, SMEM_BYTES);

    const int total4 = NX4 + NW04 + NW14;
    prep_kernel<<<(total4 + 255) / 256, 256>>>(x, w0, w1);

    dim3 grid(DD, B / BT);
    fused_mlp_hmma<<<grid, NT, SMEM_BYTES>>>(w2, b0, b1, b2, out);
}

// round 9
// speedup vs baseline: 1.5666x; 1.5666x over previous
#include <cuda_runtime.h>
#include <cuda_fp16.h>
#include <cstdint>

// Fused per-variable MLP, mma.sync m16n8k16 fp16, 2-pass split:
//   A = X rows (fp16 hi+lo, exact), B = W (single fp16, rounding 2^-11).
// Warp w: rows (w&3)*16..+16, units (w>>2)*32..+32. X loaded once per warp,
// h1 kept in registers through layer 2. Per-pair named barriers (64 thr).

#define DD 128
#define HH 64
#define OO 2
#define BT 64
#define NT 256
#define SLOPE 0.01f
#define BATCH 8192

// row strides in BYTES (conflict-free frag patterns need stride%128==16)
#define XS   272   // 128 fp16 + 8 pad
#define W0S  272
#define W1S  144   // 64 fp16 + 8 pad
#define HS   144

#define XT_BYTES  (BT*XS)      // 17408
#define W0T_BYTES (HH*W0S)     // 17408
#define W1T_BYTES (HH*W1S)     // 9216

__device__ __align__(16) unsigned char gXhi[BATCH*XS];
__device__ __align__(16) unsigned char gXlo[BATCH*XS];
__device__ __align__(16) unsigned char gW0[DD*W0T_BYTES];
__device__ __align__(16) unsigned char gW1[DD*W1T_BYTES];

// smem byte offsets
#define SM_XHI 0         // 17408
#define SM_XLO 17408     // 17408
#define SM_W0  34816     // 17408
#define SM_W1  52224     // 9216
#define SM_HHI 61440     // 9216
#define SM_HLO 70656     // 9216
#define SM_B0  79872     // 64 f32
#define SM_B1  80128     // 64 f32
#define SM_W2  80384     // 128 f32
#define SM_P   80896     // 4 pairs * 8 gid * float4 = 512
#define SMEM_BYTES 81408

static __device__ __forceinline__ void mma_f16(float acc[4], const uint32_t a[4],
                                               uint32_t b0, uint32_t b1) {
    asm volatile(
        "mma.sync.aligned.m16n8k16.row.col.f32.f16.f16.f32 "
        "{%0,%1,%2,%3}, {%4,%5,%6,%7}, {%8,%9}, {%0,%1,%2,%3};"
        : "+f"(acc[0]), "+f"(acc[1]), "+f"(acc[2]), "+f"(acc[3])
        : "r"(a[0]), "r"(a[1]), "r"(a[2]), "r"(a[3]), "r"(b0), "r"(b1));
}
static __device__ __forceinline__ void splitx2(float a, float b, uint32_t& hi, uint32_t& lo) {
    __half ah = __float2half_rn(a), bh = __float2half_rn(b);
    __half al = __float2half_rn(a - __half2float(ah));
    __half bl = __float2half_rn(b - __half2float(bh));
    __half2 h2 = __halves2half2(ah, bh), l2 = __halves2half2(al, bl);
    hi = *reinterpret_cast<uint32_t*>(&h2);
    lo = *reinterpret_cast<uint32_t*>(&l2);
}
static __device__ __forceinline__ uint32_t packh2(float a, float b) {
    __half2 h2 = __halves2half2(__float2half_rn(a), __float2half_rn(b));
    return *reinterpret_cast<uint32_t*>(&h2);
}
#define CP16(sdst, gsrc) asm volatile( \
    "cp.async.cg.shared.global [%0], [%1], 16;" :: "r"(sdst), "l"(gsrc))

// ===================== prep: split X, round+mask W =====================
#define NX4  (BATCH*DD/4)        // 262144
#define NW04 (DD*HH*DD/4)        // 262144
#define NW14 (DD*HH*HH/4)        // 131072

__global__ void __launch_bounds__(256)
prep_kernel(const float* __restrict__ x, const float* __restrict__ w0,
            const float* __restrict__ w1)
{
    int idx = blockIdx.x * 256 + threadIdx.x;
    if (idx < NX4) {
        int r = idx >> 5, c = idx & 31;
        float4 v = reinterpret_cast<const float4*>(x)[idx];
        uint32_t h0, l0, h1, l1;
        splitx2(v.x, v.y, h0, l0); splitx2(v.z, v.w, h1, l1);
        *reinterpret_cast<uint2*>(gXhi + r * XS + c * 8) = make_uint2(h0, h1);
        *reinterpret_cast<uint2*>(gXlo + r * XS + c * 8) = make_uint2(l0, l1);
    } else if (idx < NX4 + NW04) {
        int j = idx - NX4;
        int t = j >> 11, k = j & 2047;
        int i = k >> 5, c4 = k & 31;
        float4 v = reinterpret_cast<const float4*>(w0)[j];
        if (c4 == (t >> 2)) reinterpret_cast<float*>(&v)[t & 3] = 0.0f;
        *reinterpret_cast<uint2*>(gW0 + t * W0T_BYTES + i * W0S + c4 * 8) =
            make_uint2(packh2(v.x, v.y), packh2(v.z, v.w));
    } else if (idx < NX4 + NW04 + NW14) {
        int j = idx - NX4 - NW04;
        int t = j >> 10, k = j & 1023;
        int i = k >> 4, c4 = k & 15;
        float4 v = reinterpret_cast<const float4*>(w1)[j];
        *reinterpret_cast<uint2*>(gW1 + t * W1T_BYTES + i * W1S + c4 * 8) =
            make_uint2(packh2(v.x, v.y), packh2(v.z, v.w));
    }
}

// ===================== main =====================
__global__ void __launch_bounds__(NT, 2)
fused_mlp_hmma(const float* __restrict__ w2, const float* __restrict__ b0,
               const float* __restrict__ b1, const float* __restrict__ b2,
               float* __restrict__ out)
{
    extern __shared__ char smem[];
    const int t = blockIdx.x, brow0 = blockIdx.y * BT;
    const int tid = threadIdx.x, wid = tid >> 5, lid = tid & 31;
    const int gid = lid >> 2, tid4 = lid & 3;
    const int r0 = (wid & 3) * 16;         // this warp's 16 batch rows
    const int uh = wid >> 2;               // unit half: 0 -> units 0..31, 1 -> 32..63
    const int barid = 1 + (wid & 3);       // pair barrier (warps w, w+4)

    uint32_t sb;
    asm("{ .reg .u64 tt; cvta.to.shared.u64 tt, %1; cvt.u32.u64 %0, tt; }"
        : "=r"(sb) : "l"(smem));

    // ---- staging: contiguous cp.async ----
    {
        const unsigned char* xh = gXhi + (size_t)brow0 * XS;
        const unsigned char* xl = gXlo + (size_t)brow0 * XS;
        const unsigned char* w0p = gW0 + (size_t)t * W0T_BYTES;
        const unsigned char* w1p = gW1 + (size_t)t * W1T_BYTES;
        #pragma unroll
        for (int i = tid; i < XT_BYTES / 16; i += NT) {
            CP16(sb + SM_XHI + i * 16, xh + i * 16);
            CP16(sb + SM_XLO + i * 16, xl + i * 16);
            CP16(sb + SM_W0 + i * 16, w0p + i * 16);
        }
        #pragma unroll
        for (int i = tid; i < W1T_BYTES / 16; i += NT) {
            CP16(sb + SM_W1 + i * 16, w1p + i * 16);
        }
        asm volatile("cp.async.commit_group;" ::: "memory");
    }
    if (tid < HH) {
        reinterpret_cast<float*>(smem + SM_B0)[tid] = b0[t * HH + tid];
        reinterpret_cast<float*>(smem + SM_B1)[tid] = b1[t * HH + tid];
    }
    if (tid < OO * HH)
        reinterpret_cast<float*>(smem + SM_W2)[tid] = w2[(size_t)t * OO * HH + tid];
    asm volatile("cp.async.wait_group 0;" ::: "memory");
    __syncthreads();

    const float* B0f = reinterpret_cast<const float*>(smem + SM_B0);
    const float* B1f = reinterpret_cast<const float*>(smem + SM_B1);
    const float* W2f = reinterpret_cast<const float*>(smem + SM_W2);

    // ============================ LAYER 0 ============================
    // A-frags: this warp's 16 X rows (hi+lo), held in regs for all unit-tiles
    uint32_t xhf[8][4], xlf[8][4];
    {
        const char* XH = smem + SM_XHI + (r0 + gid) * XS + tid4 * 4;
        const char* XL = smem + SM_XLO + (r0 + gid) * XS + tid4 * 4;
        #pragma unroll
        for (int ks = 0; ks < 8; ks++) {
            xhf[ks][0] = *reinterpret_cast<const uint32_t*>(XH + ks * 32);
            xhf[ks][1] = *reinterpret_cast<const uint32_t*>(XH + ks * 32 + 8 * XS);
            xhf[ks][2] = *reinterpret_cast<const uint32_t*>(XH + ks * 32 + 16);
            xhf[ks][3] = *reinterpret_cast<const uint32_t*>(XH + ks * 32 + 8 * XS + 16);
            xlf[ks][0] = *reinterpret_cast<const uint32_t*>(XL + ks * 32);
            xlf[ks][1] = *reinterpret_cast<const uint32_t*>(XL + ks * 32 + 8 * XS);
            xlf[ks][2] = *reinterpret_cast<const uint32_t*>(XL + ks * 32 + 16);
            xlf[ks][3] = *reinterpret_cast<const uint32_t*>(XL + ks * 32 + 8 * XS + 16);
        }
    }
    #pragma unroll
    for (int ut = 0; ut < 4; ut++) {
        const int u0 = uh * 32 + ut * 8;
        const char* WR = smem + SM_W0 + (u0 + gid) * W0S + tid4 * 4;
        float acc[4] = {0.f, 0.f, 0.f, 0.f};
        #pragma unroll
        for (int ks = 0; ks < 8; ks++) {
            uint32_t bw0 = *reinterpret_cast<const uint32_t*>(WR + ks * 32);
            uint32_t bw1 = *reinterpret_cast<const uint32_t*>(WR + ks * 32 + 16);
            mma_f16(acc, xhf[ks], bw0, bw1);
            mma_f16(acc, xlf[ks], bw0, bw1);
        }
        const int un = u0 + 2 * tid4;
        const float bA = B0f[un], bB = B0f[un + 1];
        float v0 = acc[0] + bA, v1 = acc[1] + bB;      // row r0+gid
        float v2 = acc[2] + bA, v3 = acc[3] + bB;      // row r0+gid+8
        v0 = (v0 > 0.f) ? v0 : SLOPE * v0;
        v1 = (v1 > 0.f) ? v1 : SLOPE * v1;
        v2 = (v2 > 0.f) ? v2 : SLOPE * v2;
        v3 = (v3 > 0.f) ? v3 : SLOPE * v3;
        // split to fp16 hi/lo, store pairs (unit un, un+1) as one u32
        __half h0 = __float2half_rn(v0), h1_ = __float2half_rn(v1);
        __half h2 = __float2half_rn(v2), h3 = __float2half_rn(v3);
        float l0 = v0 - __half2float(h0), l1 = v1 - __half2float(h1_);
        float l2 = v2 - __half2float(h2), l3 = v3 - __half2float(h3);
        char* Hh = smem + SM_HHI; char* Hl = smem + SM_HLO;
        const int ra = (r0 + gid) * HS + un * 2, rb = ra + 8 * HS;
        __half2 p;
        p = __halves2half2(h0, h1_); *reinterpret_cast<uint32_t*>(Hh + ra) = *reinterpret_cast<uint32_t*>(&p);
        p = __halves2half2(h2, h3);  *reinterpret_cast<uint32_t*>(Hh + rb) = *reinterpret_cast<uint32_t*>(&p);
        p = __halves2half2(__float2half_rn(l0), __float2half_rn(l1));
        *reinterpret_cast<uint32_t*>(Hl + ra) = *reinterpret_cast<uint32_t*>(&p);
        p = __halves2half2(__float2half_rn(l2), __float2half_rn(l3));
        *reinterpret_cast<uint32_t*>(Hl + rb) = *reinterpret_cast<uint32_t*>(&p);
    }
    asm volatile("bar.sync %0, 64;" :: "r"(barid) : "memory");

    // ============================ LAYER 1 ============================
    float h1v[4][4];   // [ut][c]: bias+leaky'd outputs, kept in regs
    {
        uint32_t ahf[4][4], alf[4][4];
        const char* AH = smem + SM_HHI + (r0 + gid) * HS + tid4 * 4;
        const char* AL = smem + SM_HLO + (r0 + gid) * HS + tid4 * 4;
        #pragma unroll
        for (int ks = 0; ks < 4; ks++) {
            ahf[ks][0] = *reinterpret_cast<const uint32_t*>(AH + ks * 32);
            ahf[ks][1] = *reinterpret_cast<const uint32_t*>(AH + ks * 32 + 8 * HS);
            ahf[ks][2] = *reinterpret_cast<const uint32_t*>(AH + ks * 32 + 16);
            ahf[ks][3] = *reinterpret_cast<const uint32_t*>(AH + ks * 32 + 8 * HS + 16);
            alf[ks][0] = *reinterpret_cast<const uint32_t*>(AL + ks * 32);
            alf[ks][1] = *reinterpret_cast<const uint32_t*>(AL + ks * 32 + 8 * HS);
            alf[ks][2] = *reinterpret_cast<const uint32_t*>(AL + ks * 32 + 16);
            alf[ks][3] = *reinterpret_cast<const uint32_t*>(AL + ks * 32 + 8 * HS + 16);
        }
        #pragma unroll
        for (int ut = 0; ut < 4; ut++) {
            const int u0 = uh * 32 + ut * 8;
            const char* WR = smem + SM_W1 + (u0 + gid) * W1S + tid4 * 4;
            float acc[4] = {0.f, 0.f, 0.f, 0.f};
            #pragma unroll
            for (int ks = 0; ks < 4; ks++) {
                uint32_t bw0 = *reinterpret_cast<const uint32_t*>(WR + ks * 32);
                uint32_t bw1 = *reinterpret_cast<const uint32_t*>(WR + ks * 32 + 16);
                mma_f16(acc, ahf[ks], bw0, bw1);
                mma_f16(acc, alf[ks], bw0, bw1);
            }
            const int un = u0 + 2 * tid4;
            const float bA = B1f[un], bB = B1f[un + 1];
            float v0 = acc[0] + bA, v1 = acc[1] + bB;
            float v2 = acc[2] + bA, v3 = acc[3] + bB;
            h1v[ut][0] = (v0 > 0.f) ? v0 : SLOPE * v0;
            h1v[ut][1] = (v1 > 0.f) ? v1 : SLOPE * v1;
            h1v[ut][2] = (v2 > 0.f) ? v2 : SLOPE * v2;
            h1v[ut][3] = (v3 > 0.f) ? v3 : SLOPE * v3;
        }
    }

    // ============================ LAYER 2 ============================
    // partial dot over this thread's units; reduce over tid4; pair-exchange.
    {
        float p00 = 0.f, p01 = 0.f, p10 = 0.f, p11 = 0.f;
        #pragma unroll
        for (int ut = 0; ut < 4; ut++) {
            const int u = uh * 32 + ut * 8 + 2 * tid4;
            float2 w2o0 = *reinterpret_cast<const float2*>(W2f + u);
            float2 w2o1 = *reinterpret_cast<const float2*>(W2f + 64 + u);
            p00 += h1v[ut][0] * w2o0.x + h1v[ut][1] * w2o0.y;
            p01 += h1v[ut][0] * w2o1.x + h1v[ut][1] * w2o1.y;
            p10 += h1v[ut][2] * w2o0.x + h1v[ut][3] * w2o0.y;
            p11 += h1v[ut][2] * w2o1.x + h1v[ut][3] * w2o1.y;
        }
        #pragma unroll
        for (int d = 1; d <= 2; d <<= 1) {
            p00 += __shfl_xor_sync(0xffffffffu, p00, d);
            p01 += __shfl_xor_sync(0xffffffffu, p01, d);
            p10 += __shfl_xor_sync(0xffffffffu, p10, d);
            p11 += __shfl_xor_sync(0xffffffffu, p11, d);
        }
        float4* P = reinterpret_cast<float4*>(smem + SM_P);
        if (uh == 1 && tid4 == 0)
            P[(wid & 3) * 8 + gid] = make_float4(p00, p01, p10, p11);
        asm volatile("bar.sync %0, 64;" :: "r"(barid) : "memory");
        if (uh == 0 && tid4 == 0) {
            float4 q = P[(wid & 3) * 8 + gid];
            const float c0 = b2[t * OO], c1 = b2[t * OO + 1];
            const int rowA = brow0 + r0 + gid, rowB = rowA + 8;
            out[(size_t)rowA * (DD * OO) + t * OO]     = p00 + q.x + c0;
            out[(size_t)rowA * (DD * OO) + t * OO + 1] = p01 + q.y + c1;
            out[(size_t)rowB * (DD * OO) + t * OO]     = p10 + q.z + c0;
            out[(size_t)rowB * (DD * OO) + t * OO + 1] = p11 + q.w + c1;
        }
    }
}

extern "C" void kernel_launch(void* const* d_in, const int* in_sizes, int n_in,
                              void* d_out, int out_size)
{
    const float* x  = (const float*)d_in[0];
    const float* w0 = (const float*)d_in[1];
    const float* w1 = (const float*)d_in[2];
    const float* w2 = (const float*)d_in[3];
    const float* b0 = (const float*)d_in[4];
    const float* b1 = (const float*)d_in[5];
    const float* b2 = (const float*)d_in[6];
    float* out = (float*)d_out;

    const int B = in_sizes[0] / DD;

    cudaFuncSetAttribute(fused_mlp_hmma,
                         cudaFuncAttributeMaxDynamicSharedMemorySize, SMEM_BYTES);

    const int total4 = NX4 + NW04 + NW14;
    prep_kernel<<<(total4 + 255) / 256, 256>>>(x, w0, w1);

    dim3 grid(DD, B / BT);
    fused_mlp_hmma<<<grid, NT, SMEM_BYTES>>>(w2, b0, b1, b2, out);
}

// round 10
// speedup vs baseline: 1.7509x; 1.1176x over previous
#include <cuda_runtime.h>
#include <cuda_fp16.h>
#include <cstdint>

// Fused per-variable MLP, mma.sync m16n8k16 fp16, 2-pass split (A=X hi+lo, B=W fp16).
// R10: ks-outer/ut-inner loops (reg-lean), H aliased over dead X windows per pair,
// 63 KB smem -> 3 CTAs/SM.

#define DD 128
#define HH 64
#define OO 2
#define BT 64
#define NT 256
#define SLOPE 0.01f
#define BATCH 8192

#define XS   272
#define W0S  272
#define W1S  144
#define HS   144

#define XT_BYTES  (BT*XS)      // 17408
#define W0T_BYTES (HH*W0S)     // 17408
#define W1T_BYTES (HH*W1S)     // 9216

__device__ __align__(16) unsigned char gXhi[BATCH*XS];
__device__ __align__(16) unsigned char gXlo[BATCH*XS];
__device__ __align__(16) unsigned char gW0[DD*W0T_BYTES];
__device__ __align__(16) unsigned char gW1[DD*W1T_BYTES];

// smem byte offsets
#define SM_XHI 0         // 17408 ; pair p's H-hi window = SM_XHI + p*4352
#define SM_XLO 17408     // 17408 ; pair p's H-lo window = SM_XLO + p*4352
#define SM_W0  34816     // 17408
#define SM_W1  52224     // 9216
#define SM_B0  61440     // 64 f32
#define SM_B1  61696
#define SM_W2  61952     // 128 f32
#define SM_P   62464     // 512
#define SMEM_BYTES 62976

static __device__ __forceinline__ void mma_f16(float acc[4], const uint32_t a[4],
                                               uint32_t b0, uint32_t b1) {
    asm volatile(
        "mma.sync.aligned.m16n8k16.row.col.f32.f16.f16.f32 "
        "{%0,%1,%2,%3}, {%4,%5,%6,%7}, {%8,%9}, {%0,%1,%2,%3};"
        : "+f"(acc[0]), "+f"(acc[1]), "+f"(acc[2]), "+f"(acc[3])
        : "r"(a[0]), "r"(a[1]), "r"(a[2]), "r"(a[3]), "r"(b0), "r"(b1));
}
static __device__ __forceinline__ void splitx2(float a, float b, uint32_t& hi, uint32_t& lo) {
    __half ah = __float2half_rn(a), bh = __float2half_rn(b);
    __half al = __float2half_rn(a - __half2float(ah));
    __half bl = __float2half_rn(b - __half2float(bh));
    __half2 h2 = __halves2half2(ah, bh), l2 = __halves2half2(al, bl);
    hi = *reinterpret_cast<uint32_t*>(&h2);
    lo = *reinterpret_cast<uint32_t*>(&l2);
}
static __device__ __forceinline__ uint32_t packh2(float a, float b) {
    __half2 h2 = __halves2half2(__float2half_rn(a), __float2half_rn(b));
    return *reinterpret_cast<uint32_t*>(&h2);
}
#define CP16(sdst, gsrc) asm volatile( \
    "cp.async.cg.shared.global [%0], [%1], 16;" :: "r"(sdst), "l"(gsrc))

// ===================== prep =====================
#define NX4  (BATCH*DD/4)
#define NW04 (DD*HH*DD/4)
#define NW14 (DD*HH*HH/4)

__global__ void __launch_bounds__(256)
prep_kernel(const float* __restrict__ x, const float* __restrict__ w0,
            const float* __restrict__ w1)
{
    int idx = blockIdx.x * 256 + threadIdx.x;
    if (idx < NX4) {
        int r = idx >> 5, c = idx & 31;
        float4 v = reinterpret_cast<const float4*>(x)[idx];
        uint32_t h0, l0, h1, l1;
        splitx2(v.x, v.y, h0, l0); splitx2(v.z, v.w, h1, l1);
        *reinterpret_cast<uint2*>(gXhi + r * XS + c * 8) = make_uint2(h0, h1);
        *reinterpret_cast<uint2*>(gXlo + r * XS + c * 8) = make_uint2(l0, l1);
    } else if (idx < NX4 + NW04) {
        int j = idx - NX4;
        int t = j >> 11, k = j & 2047;
        int i = k >> 5, c4 = k & 31;
        float4 v = reinterpret_cast<const float4*>(w0)[j];
        if (c4 == (t >> 2)) reinterpret_cast<float*>(&v)[t & 3] = 0.0f;
        *reinterpret_cast<uint2*>(gW0 + t * W0T_BYTES + i * W0S + c4 * 8) =
            make_uint2(packh2(v.x, v.y), packh2(v.z, v.w));
    } else if (idx < NX4 + NW04 + NW14) {
        int j = idx - NX4 - NW04;
        int t = j >> 10, k = j & 1023;
        int i = k >> 4, c4 = k & 15;
        float4 v = reinterpret_cast<const float4*>(w1)[j];
        *reinterpret_cast<uint2*>(gW1 + t * W1T_BYTES + i * W1S + c4 * 8) =
            make_uint2(packh2(v.x, v.y), packh2(v.z, v.w));
    }
}

// ===================== main =====================
__global__ void __launch_bounds__(NT, 3)
fused_mlp_hmma(const float* __restrict__ w2, const float* __restrict__ b0,
               const float* __restrict__ b1, const float* __restrict__ b2,
               float* __restrict__ out)
{
    extern __shared__ char smem[];
    const int t = blockIdx.x, brow0 = blockIdx.y * BT;
    const int tid = threadIdx.x, wid = tid >> 5, lid = tid & 31;
    const int gid = lid >> 2, tid4 = lid & 3;
    const int pair = wid & 3;              // row-pair index
    const int r0 = pair * 16;              // this warp's 16 batch rows
    const int uh = wid >> 2;               // unit half
    const int barid = 1 + pair;            // pair barrier (warps pair, pair+4)

    uint32_t sb;
    asm("{ .reg .u64 tt; cvta.to.shared.u64 tt, %1; cvt.u32.u64 %0, tt; }"
        : "=r"(sb) : "l"(smem));

    // ---- staging ----
    {
        const unsigned char* xh = gXhi + (size_t)brow0 * XS;
        const unsigned char* xl = gXlo + (size_t)brow0 * XS;
        const unsigned char* w0p = gW0 + (size_t)t * W0T_BYTES;
        const unsigned char* w1p = gW1 + (size_t)t * W1T_BYTES;
        #pragma unroll
        for (int i = tid; i < XT_BYTES / 16; i += NT) {
            CP16(sb + SM_XHI + i * 16, xh + i * 16);
            CP16(sb + SM_XLO + i * 16, xl + i * 16);
            CP16(sb + SM_W0 + i * 16, w0p + i * 16);
        }
        #pragma unroll
        for (int i = tid; i < W1T_BYTES / 16; i += NT) {
            CP16(sb + SM_W1 + i * 16, w1p + i * 16);
        }
        asm volatile("cp.async.commit_group;" ::: "memory");
    }
    if (tid < HH) {
        reinterpret_cast<float*>(smem + SM_B0)[tid] = b0[t * HH + tid];
        reinterpret_cast<float*>(smem + SM_B1)[tid] = b1[t * HH + tid];
    }
    if (tid < OO * HH)
        reinterpret_cast<float*>(smem + SM_W2)[tid] = w2[(size_t)t * OO * HH + tid];
    asm volatile("cp.async.wait_group 0;" ::: "memory");
    __syncthreads();

    const float* B0f = reinterpret_cast<const float*>(smem + SM_B0);
    const float* B1f = reinterpret_cast<const float*>(smem + SM_B1);
    const float* W2f = reinterpret_cast<const float*>(smem + SM_W2);

    // per-pair H windows aliased over this pair's dead X rows
    char* Hh = smem + SM_XHI + pair * 4352;
    char* Hl = smem + SM_XLO + pair * 4352;

    // ============================ LAYER 0 ============================
    float acc[4][4];
    #pragma unroll
    for (int ut = 0; ut < 4; ut++)
        #pragma unroll
        for (int c = 0; c < 4; c++) acc[ut][c] = 0.f;
    {
        const char* XH = smem + SM_XHI + (r0 + gid) * XS + tid4 * 4;
        const char* XL = smem + SM_XLO + (r0 + gid) * XS + tid4 * 4;
        const char* WR = smem + SM_W0 + (uh * 32 + gid) * W0S + tid4 * 4;
        #pragma unroll
        for (int ks = 0; ks < 8; ks++) {
            uint32_t xh[4], xl[4];
            xh[0] = *reinterpret_cast<const uint32_t*>(XH + ks * 32);
            xh[1] = *reinterpret_cast<const uint32_t*>(XH + ks * 32 + 8 * XS);
            xh[2] = *reinterpret_cast<const uint32_t*>(XH + ks * 32 + 16);
            xh[3] = *reinterpret_cast<const uint32_t*>(XH + ks * 32 + 8 * XS + 16);
            xl[0] = *reinterpret_cast<const uint32_t*>(XL + ks * 32);
            xl[1] = *reinterpret_cast<const uint32_t*>(XL + ks * 32 + 8 * XS);
            xl[2] = *reinterpret_cast<const uint32_t*>(XL + ks * 32 + 16);
            xl[3] = *reinterpret_cast<const uint32_t*>(XL + ks * 32 + 8 * XS + 16);
            #pragma unroll
            for (int ut = 0; ut < 4; ut++) {
                uint32_t bw0 = *reinterpret_cast<const uint32_t*>(WR + ut * 8 * W0S + ks * 32);
                uint32_t bw1 = *reinterpret_cast<const uint32_t*>(WR + ut * 8 * W0S + ks * 32 + 16);
                mma_f16(acc[ut], xh, bw0, bw1);
                mma_f16(acc[ut], xl, bw0, bw1);
            }
        }
    }
    // pair must finish reading X before we overwrite its window with H
    asm volatile("bar.sync %0, 64;" :: "r"(barid) : "memory");
    #pragma unroll
    for (int ut = 0; ut < 4; ut++) {
        const int un = uh * 32 + ut * 8 + 2 * tid4;
        const float bA = B0f[un], bB = B0f[un + 1];
        float v0 = acc[ut][0] + bA, v1 = acc[ut][1] + bB;   // block row gid
        float v2 = acc[ut][2] + bA, v3 = acc[ut][3] + bB;   // block row gid+8
        v0 = (v0 > 0.f) ? v0 : SLOPE * v0;
        v1 = (v1 > 0.f) ? v1 : SLOPE * v1;
        v2 = (v2 > 0.f) ? v2 : SLOPE * v2;
        v3 = (v3 > 0.f) ? v3 : SLOPE * v3;
        __half h0 = __float2half_rn(v0), h1_ = __float2half_rn(v1);
        __half h2 = __float2half_rn(v2), h3 = __float2half_rn(v3);
        float l0 = v0 - __half2float(h0), l1 = v1 - __half2float(h1_);
        float l2 = v2 - __half2float(h2), l3 = v3 - __half2float(h3);
        const int ra = gid * HS + un * 2, rb = ra + 8 * HS;
        __half2 p;
        p = __halves2half2(h0, h1_); *reinterpret_cast<uint32_t*>(Hh + ra) = *reinterpret_cast<uint32_t*>(&p);
        p = __halves2half2(h2, h3);  *reinterpret_cast<uint32_t*>(Hh + rb) = *reinterpret_cast<uint32_t*>(&p);
        p = __halves2half2(__float2half_rn(l0), __float2half_rn(l1));
        *reinterpret_cast<uint32_t*>(Hl + ra) = *reinterpret_cast<uint32_t*>(&p);
        p = __halves2half2(__float2half_rn(l2), __float2half_rn(l3));
        *reinterpret_cast<uint32_t*>(Hl + rb) = *reinterpret_cast<uint32_t*>(&p);
    }
    asm volatile("bar.sync %0, 64;" :: "r"(barid) : "memory");

    // ============================ LAYER 1 ============================
    float h1v[4][4];
    #pragma unroll
    for (int ut = 0; ut < 4; ut++)
        #pragma unroll
        for (int c = 0; c < 4; c++) h1v[ut][c] = 0.f;
    {
        const char* AH = Hh + gid * HS + tid4 * 4;
        const char* AL = Hl + gid * HS + tid4 * 4;
        const char* WR = smem + SM_W1 + (uh * 32 + gid) * W1S + tid4 * 4;
        #pragma unroll
        for (int ks = 0; ks < 4; ks++) {
            uint32_t ah[4], al[4];
            ah[0] = *reinterpret_cast<const uint32_t*>(AH + ks * 32);
            ah[1] = *reinterpret_cast<const uint32_t*>(AH + ks * 32 + 8 * HS);
            ah[2] = *reinterpret_cast<const uint32_t*>(AH + ks * 32 + 16);
            ah[3] = *reinterpret_cast<const uint32_t*>(AH + ks * 32 + 8 * HS + 16);
            al[0] = *reinterpret_cast<const uint32_t*>(AL + ks * 32);
            al[1] = *reinterpret_cast<const uint32_t*>(AL + ks * 32 + 8 * HS);
            al[2] = *reinterpret_cast<const uint32_t*>(AL + ks * 32 + 16);
            al[3] = *reinterpret_cast<const uint32_t*>(AL + ks * 32 + 8 * HS + 16);
            #pragma unroll
            for (int ut = 0; ut < 4; ut++) {
                uint32_t bw0 = *reinterpret_cast<const uint32_t*>(WR + ut * 8 * W1S + ks * 32);
                uint32_t bw1 = *reinterpret_cast<const uint32_t*>(WR + ut * 8 * W1S + ks * 32 + 16);
                mma_f16(h1v[ut], ah, bw0, bw1);
                mma_f16(h1v[ut], al, bw0, bw1);
            }
        }
    }
    #pragma unroll
    for (int ut = 0; ut < 4; ut++) {
        const int un = uh * 32 + ut * 8 + 2 * tid4;
        const float bA = B1f[un], bB = B1f[un + 1];
        float v0 = h1v[ut][0] + bA, v1 = h1v[ut][1] + bB;
        float v2 = h1v[ut][2] + bA, v3 = h1v[ut][3] + bB;
        h1v[ut][0] = (v0 > 0.f) ? v0 : SLOPE * v0;
        h1v[ut][1] = (v1 > 0.f) ? v1 : SLOPE * v1;
        h1v[ut][2] = (v2 > 0.f) ? v2 : SLOPE * v2;
        h1v[ut][3] = (v3 > 0.f) ? v3 : SLOPE * v3;
    }

    // ============================ LAYER 2 ============================
    {
        float p00 = 0.f, p01 = 0.f, p10 = 0.f, p11 = 0.f;
        #pragma unroll
        for (int ut = 0; ut < 4; ut++) {
            const int u = uh * 32 + ut * 8 + 2 * tid4;
            float2 w2o0 = *reinterpret_cast<const float2*>(W2f + u);
            float2 w2o1 = *reinterpret_cast<const float2*>(W2f + 64 + u);
            p00 += h1v[ut][0] * w2o0.x + h1v[ut][1] * w2o0.y;
            p01 += h1v[ut][0] * w2o1.x + h1v[ut][1] * w2o1.y;
            p10 += h1v[ut][2] * w2o0.x + h1v[ut][3] * w2o0.y;
            p11 += h1v[ut][2] * w2o1.x + h1v[ut][3] * w2o1.y;
        }
        #pragma unroll
        for (int d = 1; d <= 2; d <<= 1) {
            p00 += __shfl_xor_sync(0xffffffffu, p00, d);
            p01 += __shfl_xor_sync(0xffffffffu, p01, d);
            p10 += __shfl_xor_sync(0xffffffffu, p10, d);
            p11 += __shfl_xor_sync(0xffffffffu, p11, d);
        }
        float4* P = reinterpret_cast<float4*>(smem + SM_P);
        if (uh == 1 && tid4 == 0)
            P[pair * 8 + gid] = make_float4(p00, p01, p10, p11);
        asm volatile("bar.sync %0, 64;" :: "r"(barid) : "memory");
        if (uh == 0 && tid4 == 0) {
            float4 q = P[pair * 8 + gid];
            const float c0 = b2[t * OO], c1 = b2[t * OO + 1];
            const int rowA = brow0 + r0 + gid, rowB = rowA + 8;
            out[(size_t)rowA * (DD * OO) + t * OO]     = p00 + q.x + c0;
            out[(size_t)rowA * (DD * OO) + t * OO + 1] = p01 + q.y + c1;
            out[(size_t)rowB * (DD * OO) + t * OO]     = p10 + q.z + c0;
            out[(size_t)rowB * (DD * OO) + t * OO + 1] = p11 + q.w + c1;
        }
    }
}

extern "C" void kernel_launch(void* const* d_in, const int* in_sizes, int n_in,
                              void* d_out, int out_size)
{
    const float* x  = (const float*)d_in[0];
    const float* w0 = (const float*)d_in[1];
    const float* w1 = (const float*)d_in[2];
    const float* w2 = (const float*)d_in[3];
    const float* b0 = (const float*)d_in[4];
    const float* b1 = (const float*)d_in[5];
    const float* b2 = (const float*)d_in[6];
    float* out = (float*)d_out;

    const int B = in_sizes[0] / DD;

    cudaFuncSetAttribute(fused_mlp_hmma,
                         cudaFuncAttributeMaxDynamicSharedMemorySize, SMEM_BYTES);

    const int total4 = NX4 + NW04 + NW14;
    prep_kernel<<<(total4 + 255) / 256, 256>>>(x, w0, w1);

    dim3 grid(DD, B / BT);
    fused_mlp_hmma<<<grid, NT, SMEM_BYTES>>>(w2, b0, b1, b2, out);
}

// round 11
// speedup vs baseline: 1.9067x; 1.0890x over previous
#include <cuda_runtime.h>
#include <cuda_fp16.h>
#include <cstdint>

// Fused per-variable MLP, mma.sync m16n8k16 fp16.
// L0: X split hi+lo (exact), W0 fp16 (2-pass).  L1: H rounded fp16, W1 fp16 (1-pass).
// R11: drop H hi/lo split -> 16 fewer MMAs + fewer LDS/stores per warp.
// ks-outer reg-lean loops, H aliased over dead X window, 3 CTAs/SM.

#define DD 128
#define HH 64
#define OO 2
#define BT 64
#define NT 256
#define SLOPE 0.01f
#define BATCH 8192

#define XS   272
#define W0S  272
#define W1S  144
#define HS   144

#define XT_BYTES  (BT*XS)      // 17408
#define W0T_BYTES (HH*W0S)     // 17408
#define W1T_BYTES (HH*W1S)     // 9216

__device__ __align__(16) unsigned char gXhi[BATCH*XS];
__device__ __align__(16) unsigned char gXlo[BATCH*XS];
__device__ __align__(16) unsigned char gW0[DD*W0T_BYTES];
__device__ __align__(16) unsigned char gW1[DD*W1T_BYTES];

// smem byte offsets
#define SM_XHI 0         // 17408 ; pair p's H window = SM_XHI + p*4352
#define SM_XLO 17408     // 17408
#define SM_W0  34816     // 17408
#define SM_W1  52224     // 9216
#define SM_B0  61440
#define SM_B1  61696
#define SM_W2  61952
#define SM_P   62464
#define SMEM_BYTES 62976

static __device__ __forceinline__ void mma_f16(float acc[4], const uint32_t a[4],
                                               uint32_t b0, uint32_t b1) {
    asm volatile(
        "mma.sync.aligned.m16n8k16.row.col.f32.f16.f16.f32 "
        "{%0,%1,%2,%3}, {%4,%5,%6,%7}, {%8,%9}, {%0,%1,%2,%3};"
        : "+f"(acc[0]), "+f"(acc[1]), "+f"(acc[2]), "+f"(acc[3])
        : "r"(a[0]), "r"(a[1]), "r"(a[2]), "r"(a[3]), "r"(b0), "r"(b1));
}
static __device__ __forceinline__ void splitx2(float a, float b, uint32_t& hi, uint32_t& lo) {
    __half ah = __float2half_rn(a), bh = __float2half_rn(b);
    __half al = __float2half_rn(a - __half2float(ah));
    __half bl = __float2half_rn(b - __half2float(bh));
    __half2 h2 = __halves2half2(ah, bh), l2 = __halves2half2(al, bl);
    hi = *reinterpret_cast<uint32_t*>(&h2);
    lo = *reinterpret_cast<uint32_t*>(&l2);
}
static __device__ __forceinline__ uint32_t packh2(float a, float b) {
    __half2 h2 = __halves2half2(__float2half_rn(a), __float2half_rn(b));
    return *reinterpret_cast<uint32_t*>(&h2);
}
#define CP16(sdst, gsrc) asm volatile( \
    "cp.async.cg.shared.global [%0], [%1], 16;" :: "r"(sdst), "l"(gsrc))

// ===================== prep =====================
#define NX4  (BATCH*DD/4)
#define NW04 (DD*HH*DD/4)
#define NW14 (DD*HH*HH/4)

__global__ void __launch_bounds__(256)
prep_kernel(const float* __restrict__ x, const float* __restrict__ w0,
            const float* __restrict__ w1)
{
    int idx = blockIdx.x * 256 + threadIdx.x;
    if (idx < NX4) {
        int r = idx >> 5, c = idx & 31;
        float4 v = reinterpret_cast<const float4*>(x)[idx];
        uint32_t h0, l0, h1, l1;
        splitx2(v.x, v.y, h0, l0); splitx2(v.z, v.w, h1, l1);
        *reinterpret_cast<uint2*>(gXhi + r * XS + c * 8) = make_uint2(h0, h1);
        *reinterpret_cast<uint2*>(gXlo + r * XS + c * 8) = make_uint2(l0, l1);
    } else if (idx < NX4 + NW04) {
        int j = idx - NX4;
        int t = j >> 11, k = j & 2047;
        int i = k >> 5, c4 = k & 31;
        float4 v = reinterpret_cast<const float4*>(w0)[j];
        if (c4 == (t >> 2)) reinterpret_cast<float*>(&v)[t & 3] = 0.0f;
        *reinterpret_cast<uint2*>(gW0 + t * W0T_BYTES + i * W0S + c4 * 8) =
            make_uint2(packh2(v.x, v.y), packh2(v.z, v.w));
    } else if (idx < NX4 + NW04 + NW14) {
        int j = idx - NX4 - NW04;
        int t = j >> 10, k = j & 1023;
        int i = k >> 4, c4 = k & 15;
        float4 v = reinterpret_cast<const float4*>(w1)[j];
        *reinterpret_cast<uint2*>(gW1 + t * W1T_BYTES + i * W1S + c4 * 8) =
            make_uint2(packh2(v.x, v.y), packh2(v.z, v.w));
    }
}

// ===================== main =====================
__global__ void __launch_bounds__(NT, 3)
fused_mlp_hmma(const float* __restrict__ w2, const float* __restrict__ b0,
               const float* __restrict__ b1, const float* __restrict__ b2,
               float* __restrict__ out)
{
    extern __shared__ char smem[];
    const int t = blockIdx.x, brow0 = blockIdx.y * BT;
    const int tid = threadIdx.x, wid = tid >> 5, lid = tid & 31;
    const int gid = lid >> 2, tid4 = lid & 3;
    const int pair = wid & 3;
    const int r0 = pair * 16;
    const int uh = wid >> 2;
    const int barid = 1 + pair;

    uint32_t sb;
    asm("{ .reg .u64 tt; cvta.to.shared.u64 tt, %1; cvt.u32.u64 %0, tt; }"
        : "=r"(sb) : "l"(smem));

    // ---- staging ----
    {
        const unsigned char* xh = gXhi + (size_t)brow0 * XS;
        const unsigned char* xl = gXlo + (size_t)brow0 * XS;
        const unsigned char* w0p = gW0 + (size_t)t * W0T_BYTES;
        const unsigned char* w1p = gW1 + (size_t)t * W1T_BYTES;
        #pragma unroll
        for (int i = tid; i < XT_BYTES / 16; i += NT) {
            CP16(sb + SM_XHI + i * 16, xh + i * 16);
            CP16(sb + SM_XLO + i * 16, xl + i * 16);
            CP16(sb + SM_W0 + i * 16, w0p + i * 16);
        }
        #pragma unroll
        for (int i = tid; i < W1T_BYTES / 16; i += NT) {
            CP16(sb + SM_W1 + i * 16, w1p + i * 16);
        }
        asm volatile("cp.async.commit_group;" ::: "memory");
    }
    if (tid < HH) {
        reinterpret_cast<float*>(smem + SM_B0)[tid] = b0[t * HH + tid];
        reinterpret_cast<float*>(smem + SM_B1)[tid] = b1[t * HH + tid];
    }
    if (tid < OO * HH)
        reinterpret_cast<float*>(smem + SM_W2)[tid] = w2[(size_t)t * OO * HH + tid];
    asm volatile("cp.async.wait_group 0;" ::: "memory");
    __syncthreads();

    const float* B0f = reinterpret_cast<const float*>(smem + SM_B0);
    const float* B1f = reinterpret_cast<const float*>(smem + SM_B1);
    const float* W2f = reinterpret_cast<const float*>(smem + SM_W2);

    // per-pair H window aliased over this pair's dead X-hi rows
    char* Hh = smem + SM_XHI + pair * 4352;

    // ============================ LAYER 0 ============================
    float acc[4][4];
    #pragma unroll
    for (int ut = 0; ut < 4; ut++)
        #pragma unroll
        for (int c = 0; c < 4; c++) acc[ut][c] = 0.f;
    {
        const char* XH = smem + SM_XHI + (r0 + gid) * XS + tid4 * 4;
        const char* XL = smem + SM_XLO + (r0 + gid) * XS + tid4 * 4;
        const char* WR = smem + SM_W0 + (uh * 32 + gid) * W0S + tid4 * 4;
        #pragma unroll
        for (int ks = 0; ks < 8; ks++) {
            uint32_t xh[4], xl[4];
            xh[0] = *reinterpret_cast<const uint32_t*>(XH + ks * 32);
            xh[1] = *reinterpret_cast<const uint32_t*>(XH + ks * 32 + 8 * XS);
            xh[2] = *reinterpret_cast<const uint32_t*>(XH + ks * 32 + 16);
            xh[3] = *reinterpret_cast<const uint32_t*>(XH + ks * 32 + 8 * XS + 16);
            xl[0] = *reinterpret_cast<const uint32_t*>(XL + ks * 32);
            xl[1] = *reinterpret_cast<const uint32_t*>(XL + ks * 32 + 8 * XS);
            xl[2] = *reinterpret_cast<const uint32_t*>(XL + ks * 32 + 16);
            xl[3] = *reinterpret_cast<const uint32_t*>(XL + ks * 32 + 8 * XS + 16);
            #pragma unroll
            for (int ut = 0; ut < 4; ut++) {
                uint32_t bw0 = *reinterpret_cast<const uint32_t*>(WR + ut * 8 * W0S + ks * 32);
                uint32_t bw1 = *reinterpret_cast<const uint32_t*>(WR + ut * 8 * W0S + ks * 32 + 16);
                mma_f16(acc[ut], xh, bw0, bw1);
                mma_f16(acc[ut], xl, bw0, bw1);
            }
        }
    }
    // pair must finish reading X before H overwrites its window
    asm volatile("bar.sync %0, 64;" :: "r"(barid) : "memory");
    #pragma unroll
    for (int ut = 0; ut < 4; ut++) {
        const int un = uh * 32 + ut * 8 + 2 * tid4;
        const float bA = B0f[un], bB = B0f[un + 1];
        float v0 = acc[ut][0] + bA, v1 = acc[ut][1] + bB;   // block row gid
        float v2 = acc[ut][2] + bA, v3 = acc[ut][3] + bB;   // block row gid+8
        v0 = (v0 > 0.f) ? v0 : SLOPE * v0;
        v1 = (v1 > 0.f) ? v1 : SLOPE * v1;
        v2 = (v2 > 0.f) ? v2 : SLOPE * v2;
        v3 = (v3 > 0.f) ? v3 : SLOPE * v3;
        const int ra = gid * HS + un * 2, rb = ra + 8 * HS;
        *reinterpret_cast<uint32_t*>(Hh + ra) = packh2(v0, v1);
        *reinterpret_cast<uint32_t*>(Hh + rb) = packh2(v2, v3);
    }
    asm volatile("bar.sync %0, 64;" :: "r"(barid) : "memory");

    // ============================ LAYER 1 (1-pass on H) ============================
    float h1v[4][4];
    #pragma unroll
    for (int ut = 0; ut < 4; ut++)
        #pragma unroll
        for (int c = 0; c < 4; c++) h1v[ut][c] = 0.f;
    {
        const char* AH = Hh + gid * HS + tid4 * 4;
        const char* WR = smem + SM_W1 + (uh * 32 + gid) * W1S + tid4 * 4;
        #pragma unroll
        for (int ks = 0; ks < 4; ks++) {
            uint32_t ah[4];
            ah[0] = *reinterpret_cast<const uint32_t*>(AH + ks * 32);
            ah[1] = *reinterpret_cast<const uint32_t*>(AH + ks * 32 + 8 * HS);
            ah[2] = *reinterpret_cast<const uint32_t*>(AH + ks * 32 + 16);
            ah[3] = *reinterpret_cast<const uint32_t*>(AH + ks * 32 + 8 * HS + 16);
            #pragma unroll
            for (int ut = 0; ut < 4; ut++) {
                uint32_t bw0 = *reinterpret_cast<const uint32_t*>(WR + ut * 8 * W1S + ks * 32);
                uint32_t bw1 = *reinterpret_cast<const uint32_t*>(WR + ut * 8 * W1S + ks * 32 + 16);
                mma_f16(h1v[ut], ah, bw0, bw1);
            }
        }
    }
    #pragma unroll
    for (int ut = 0; ut < 4; ut++) {
        const int un = uh * 32 + ut * 8 + 2 * tid4;
        const float bA = B1f[un], bB = B1f[un + 1];
        float v0 = h1v[ut][0] + bA, v1 = h1v[ut][1] + bB;
        float v2 = h1v[ut][2] + bA, v3 = h1v[ut][3] + bB;
        h1v[ut][0] = (v0 > 0.f) ? v0 : SLOPE * v0;
        h1v[ut][1] = (v1 > 0.f) ? v1 : SLOPE * v1;
        h1v[ut][2] = (v2 > 0.f) ? v2 : SLOPE * v2;
        h1v[ut][3] = (v3 > 0.f) ? v3 : SLOPE * v3;
    }

    // ============================ LAYER 2 ============================
    {
        float p00 = 0.f, p01 = 0.f, p10 = 0.f, p11 = 0.f;
        #pragma unroll
        for (int ut = 0; ut < 4; ut++) {
            const int u = uh * 32 + ut * 8 + 2 * tid4;
            float2 w2o0 = *reinterpret_cast<const float2*>(W2f + u);
            float2 w2o1 = *reinterpret_cast<const float2*>(W2f + 64 + u);
            p00 += h1v[ut][0] * w2o0.x + h1v[ut][1] * w2o0.y;
            p01 += h1v[ut][0] * w2o1.x + h1v[ut][1] * w2o1.y;
            p10 += h1v[ut][2] * w2o0.x + h1v[ut][3] * w2o0.y;
            p11 += h1v[ut][2] * w2o1.x + h1v[ut][3] * w2o1.y;
        }
        #pragma unroll
        for (int d = 1; d <= 2; d <<= 1) {
            p00 += __shfl_xor_sync(0xffffffffu, p00, d);
            p01 += __shfl_xor_sync(0xffffffffu, p01, d);
            p10 += __shfl_xor_sync(0xffffffffu, p10, d);
            p11 += __shfl_xor_sync(0xffffffffu, p11, d);
        }
        float4* P = reinterpret_cast<float4*>(smem + SM_P);
        if (uh == 1 && tid4 == 0)
            P[pair * 8 + gid] = make_float4(p00, p01, p10, p11);
        asm volatile("bar.sync %0, 64;" :: "r"(barid) : "memory");
        if (uh == 0 && tid4 == 0) {
            float4 q = P[pair * 8 + gid];
            const float c0 = b2[t * OO], c1 = b2[t * OO + 1];
            const int rowA = brow0 + r0 + gid, rowB = rowA + 8;
            out[(size_t)rowA * (DD * OO) + t * OO]     = p00 + q.x + c0;
            out[(size_t)rowA * (DD * OO) + t * OO + 1] = p01 + q.y + c1;
            out[(size_t)rowB * (DD * OO) + t * OO]     = p10 + q.z + c0;
            out[(size_t)rowB * (DD * OO) + t * OO + 1] = p11 + q.w + c1;
        }
    }
}

extern "C" void kernel_launch(void* const* d_in, const int* in_sizes, int n_in,
                              void* d_out, int out_size)
{
    const float* x  = (const float*)d_in[0];
    const float* w0 = (const float*)d_in[1];
    const float* w1 = (const float*)d_in[2];
    const float* w2 = (const float*)d_in[3];
    const float* b0 = (const float*)d_in[4];
    const float* b1 = (const float*)d_in[5];
    const float* b2 = (const float*)d_in[6];
    float* out = (float*)d_out;

    const int B = in_sizes[0] / DD;

    cudaFuncSetAttribute(fused_mlp_hmma,
                         cudaFuncAttributeMaxDynamicSharedMemorySize, SMEM_BYTES);

    const int total4 = NX4 + NW04 + NW14;
    prep_kernel<<<(total4 + 255) / 256, 256>>>(x, w0, w1);

    dim3 grid(DD, B / BT);
    fused_mlp_hmma<<<grid, NT, SMEM_BYTES>>>(w2, b0, b1, b2, out);
}

// round 12
// speedup vs baseline: 2.2753x; 1.1933x over previous
#include <cuda_runtime.h>
#include <cuda_fp16.h>
#include <cstdint>

// Fused per-variable MLP, mma.sync m16n8k16 fp16, all operands single fp16
// (X, W0, W1, H), fp32 accumulate. Error ~3e-4 << 1e-3 gate.
// R12: drop X hi/lo split -> 32 fewer MMAs + fewer LDS + less staging.
// ks-outer reg-lean loops, H aliased over dead X window, 3 CTAs/SM.

#define DD 128
#define HH 64
#define OO 2
#define BT 64
#define NT 256
#define SLOPE 0.01f
#define BATCH 8192

#define XS   272
#define W0S  272
#define W1S  144
#define HS   144

#define XT_BYTES  (BT*XS)      // 17408
#define W0T_BYTES (HH*W0S)     // 17408
#define W1T_BYTES (HH*W1S)     // 9216

__device__ __align__(16) unsigned char gX[BATCH*XS];
__device__ __align__(16) unsigned char gW0[DD*W0T_BYTES];
__device__ __align__(16) unsigned char gW1[DD*W1T_BYTES];

// smem byte offsets
#define SM_X   0         // 17408 ; pair p's H window = SM_X + p*4352
#define SM_W0  17408     // 17408
#define SM_W1  34816     // 9216
#define SM_B0  44032
#define SM_B1  44288
#define SM_W2  44544     // 128 f32
#define SM_P   45056     // 512
#define SMEM_BYTES 45568

static __device__ __forceinline__ void mma_f16(float acc[4], const uint32_t a[4],
                                               uint32_t b0, uint32_t b1) {
    asm volatile(
        "mma.sync.aligned.m16n8k16.row.col.f32.f16.f16.f32 "
        "{%0,%1,%2,%3}, {%4,%5,%6,%7}, {%8,%9}, {%0,%1,%2,%3};"
        : "+f"(acc[0]), "+f"(acc[1]), "+f"(acc[2]), "+f"(acc[3])
        : "r"(a[0]), "r"(a[1]), "r"(a[2]), "r"(a[3]), "r"(b0), "r"(b1));
}
static __device__ __forceinline__ uint32_t packh2(float a, float b) {
    __half2 h2 = __halves2half2(__float2half_rn(a), __float2half_rn(b));
    return *reinterpret_cast<uint32_t*>(&h2);
}
#define CP16(sdst, gsrc) asm volatile( \
    "cp.async.cg.shared.global [%0], [%1], 16;" :: "r"(sdst), "l"(gsrc))

// ===================== prep =====================
#define NX4  (BATCH*DD/4)
#define NW04 (DD*HH*DD/4)
#define NW14 (DD*HH*HH/4)

__global__ void __launch_bounds__(256)
prep_kernel(const float* __restrict__ x, const float* __restrict__ w0,
            const float* __restrict__ w1)
{
    int idx = blockIdx.x * 256 + threadIdx.x;
    if (idx < NX4) {
        int r = idx >> 5, c = idx & 31;
        float4 v = reinterpret_cast<const float4*>(x)[idx];
        *reinterpret_cast<uint2*>(gX + r * XS + c * 8) =
            make_uint2(packh2(v.x, v.y), packh2(v.z, v.w));
    } else if (idx < NX4 + NW04) {
        int j = idx - NX4;
        int t = j >> 11, k = j & 2047;
        int i = k >> 5, c4 = k & 31;
        float4 v = reinterpret_cast<const float4*>(w0)[j];
        if (c4 == (t >> 2)) reinterpret_cast<float*>(&v)[t & 3] = 0.0f;
        *reinterpret_cast<uint2*>(gW0 + t * W0T_BYTES + i * W0S + c4 * 8) =
            make_uint2(packh2(v.x, v.y), packh2(v.z, v.w));
    } else if (idx < NX4 + NW04 + NW14) {
        int j = idx - NX4 - NW04;
        int t = j >> 10, k = j & 1023;
        int i = k >> 4, c4 = k & 15;
        float4 v = reinterpret_cast<const float4*>(w1)[j];
        *reinterpret_cast<uint2*>(gW1 + t * W1T_BYTES + i * W1S + c4 * 8) =
            make_uint2(packh2(v.x, v.y), packh2(v.z, v.w));
    }
}

// ===================== main =====================
__global__ void __launch_bounds__(NT, 3)
fused_mlp_hmma(const float* __restrict__ w2, const float* __restrict__ b0,
               const float* __restrict__ b1, const float* __restrict__ b2,
               float* __restrict__ out)
{
    extern __shared__ char smem[];
    const int t = blockIdx.x, brow0 = blockIdx.y * BT;
    const int tid = threadIdx.x, wid = tid >> 5, lid = tid & 31;
    const int gid = lid >> 2, tid4 = lid & 3;
    const int pair = wid & 3;
    const int r0 = pair * 16;
    const int uh = wid >> 2;
    const int barid = 1 + pair;

    uint32_t sb;
    asm("{ .reg .u64 tt; cvta.to.shared.u64 tt, %1; cvt.u32.u64 %0, tt; }"
        : "=r"(sb) : "l"(smem));

    // ---- staging ----
    {
        const unsigned char* xp = gX + (size_t)brow0 * XS;
        const unsigned char* w0p = gW0 + (size_t)t * W0T_BYTES;
        const unsigned char* w1p = gW1 + (size_t)t * W1T_BYTES;
        #pragma unroll
        for (int i = tid; i < XT_BYTES / 16; i += NT) {
            CP16(sb + SM_X + i * 16, xp + i * 16);
            CP16(sb + SM_W0 + i * 16, w0p + i * 16);
        }
        #pragma unroll
        for (int i = tid; i < W1T_BYTES / 16; i += NT) {
            CP16(sb + SM_W1 + i * 16, w1p + i * 16);
        }
        asm volatile("cp.async.commit_group;" ::: "memory");
    }
    if (tid < HH) {
        reinterpret_cast<float*>(smem + SM_B0)[tid] = b0[t * HH + tid];
        reinterpret_cast<float*>(smem + SM_B1)[tid] = b1[t * HH + tid];
    }
    if (tid < OO * HH)
        reinterpret_cast<float*>(smem + SM_W2)[tid] = w2[(size_t)t * OO * HH + tid];
    asm volatile("cp.async.wait_group 0;" ::: "memory");
    __syncthreads();

    const float* B0f = reinterpret_cast<const float*>(smem + SM_B0);
    const float* B1f = reinterpret_cast<const float*>(smem + SM_B1);
    const float* W2f = reinterpret_cast<const float*>(smem + SM_W2);

    // per-pair H window aliased over this pair's dead X rows
    char* Hh = smem + SM_X + pair * 4352;

    // ============================ LAYER 0 (1-pass X) ============================
    float acc[4][4];
    #pragma unroll
    for (int ut = 0; ut < 4; ut++)
        #pragma unroll
        for (int c = 0; c < 4; c++) acc[ut][c] = 0.f;
    {
        const char* XH = smem + SM_X + (r0 + gid) * XS + tid4 * 4;
        const char* WR = smem + SM_W0 + (uh * 32 + gid) * W0S + tid4 * 4;
        #pragma unroll
        for (int ks = 0; ks < 8; ks++) {
            uint32_t xh[4];
            xh[0] = *reinterpret_cast<const uint32_t*>(XH + ks * 32);
            xh[1] = *reinterpret_cast<const uint32_t*>(XH + ks * 32 + 8 * XS);
            xh[2] = *reinterpret_cast<const uint32_t*>(XH + ks * 32 + 16);
            xh[3] = *reinterpret_cast<const uint32_t*>(XH + ks * 32 + 8 * XS + 16);
            #pragma unroll
            for (int ut = 0; ut < 4; ut++) {
                uint32_t bw0 = *reinterpret_cast<const uint32_t*>(WR + ut * 8 * W0S + ks * 32);
                uint32_t bw1 = *reinterpret_cast<const uint32_t*>(WR + ut * 8 * W0S + ks * 32 + 16);
                mma_f16(acc[ut], xh, bw0, bw1);
            }
        }
    }
    // pair must finish reading X before H overwrites its window
    asm volatile("bar.sync %0, 64;" :: "r"(barid) : "memory");
    #pragma unroll
    for (int ut = 0; ut < 4; ut++) {
        const int un = uh * 32 + ut * 8 + 2 * tid4;
        const float bA = B0f[un], bB = B0f[un + 1];
        float v0 = acc[ut][0] + bA, v1 = acc[ut][1] + bB;   // block row gid
        float v2 = acc[ut][2] + bA, v3 = acc[ut][3] + bB;   // block row gid+8
        v0 = (v0 > 0.f) ? v0 : SLOPE * v0;
        v1 = (v1 > 0.f) ? v1 : SLOPE * v1;
        v2 = (v2 > 0.f) ? v2 : SLOPE * v2;
        v3 = (v3 > 0.f) ? v3 : SLOPE * v3;
        const int ra = gid * HS + un * 2, rb = ra + 8 * HS;
        *reinterpret_cast<uint32_t*>(Hh + ra) = packh2(v0, v1);
        *reinterpret_cast<uint32_t*>(Hh + rb) = packh2(v2, v3);
    }
    asm volatile("bar.sync %0, 64;" :: "r"(barid) : "memory");

    // ============================ LAYER 1 (1-pass H) ============================
    float h1v[4][4];
    #pragma unroll
    for (int ut = 0; ut < 4; ut++)
        #pragma unroll
        for (int c = 0; c < 4; c++) h1v[ut][c] = 0.f;
    {
        const char* AH = Hh + gid * HS + tid4 * 4;
        const char* WR = smem + SM_W1 + (uh * 32 + gid) * W1S + tid4 * 4;
        #pragma unroll
        for (int ks = 0; ks < 4; ks++) {
            uint32_t ah[4];
            ah[0] = *reinterpret_cast<const uint32_t*>(AH + ks * 32);
            ah[1] = *reinterpret_cast<const uint32_t*>(AH + ks * 32 + 8 * HS);
            ah[2] = *reinterpret_cast<const uint32_t*>(AH + ks * 32 + 16);
            ah[3] = *reinterpret_cast<const uint32_t*>(AH + ks * 32 + 8 * HS + 16);
            #pragma unroll
            for (int ut = 0; ut < 4; ut++) {
                uint32_t bw0 = *reinterpret_cast<const uint32_t*>(WR + ut * 8 * W1S + ks * 32);
                uint32_t bw1 = *reinterpret_cast<const uint32_t*>(WR + ut * 8 * W1S + ks * 32 + 16);
                mma_f16(h1v[ut], ah, bw0, bw1);
            }
        }
    }
    #pragma unroll
    for (int ut = 0; ut < 4; ut++) {
        const int un = uh * 32 + ut * 8 + 2 * tid4;
        const float bA = B1f[un], bB = B1f[un + 1];
        float v0 = h1v[ut][0] + bA, v1 = h1v[ut][1] + bB;
        float v2 = h1v[ut][2] + bA, v3 = h1v[ut][3] + bB;
        h1v[ut][0] = (v0 > 0.f) ? v0 : SLOPE * v0;
        h1v[ut][1] = (v1 > 0.f) ? v1 : SLOPE * v1;
        h1v[ut][2] = (v2 > 0.f) ? v2 : SLOPE * v2;
        h1v[ut][3] = (v3 > 0.f) ? v3 : SLOPE * v3;
    }

    // ============================ LAYER 2 ============================
    {
        float p00 = 0.f, p01 = 0.f, p10 = 0.f, p11 = 0.f;
        #pragma unroll
        for (int ut = 0; ut < 4; ut++) {
            const int u = uh * 32 + ut * 8 + 2 * tid4;
            float2 w2o0 = *reinterpret_cast<const float2*>(W2f + u);
            float2 w2o1 = *reinterpret_cast<const float2*>(W2f + 64 + u);
            p00 += h1v[ut][0] * w2o0.x + h1v[ut][1] * w2o0.y;
            p01 += h1v[ut][0] * w2o1.x + h1v[ut][1] * w2o1.y;
            p10 += h1v[ut][2] * w2o0.x + h1v[ut][3] * w2o0.y;
            p11 += h1v[ut][2] * w2o1.x + h1v[ut][3] * w2o1.y;
        }
        #pragma unroll
        for (int d = 1; d <= 2; d <<= 1) {
            p00 += __shfl_xor_sync(0xffffffffu, p00, d);
            p01 += __shfl_xor_sync(0xffffffffu, p01, d);
            p10 += __shfl_xor_sync(0xffffffffu, p10, d);
            p11 += __shfl_xor_sync(0xffffffffu, p11, d);
        }
        float4* P = reinterpret_cast<float4*>(smem + SM_P);
        if (uh == 1 && tid4 == 0)
            P[pair * 8 + gid] = make_float4(p00, p01, p10, p11);
        asm volatile("bar.sync %0, 64;" :: "r"(barid) : "memory");
        if (uh == 0 && tid4 == 0) {
            float4 q = P[pair * 8 + gid];
            const float c0 = b2[t * OO], c1 = b2[t * OO + 1];
            const int rowA = brow0 + r0 + gid, rowB = rowA + 8;
            out[(size_t)rowA * (DD * OO) + t * OO]     = p00 + q.x + c0;
            out[(size_t)rowA * (DD * OO) + t * OO + 1] = p01 + q.y + c1;
            out[(size_t)rowB * (DD * OO) + t * OO]     = p10 + q.z + c0;
            out[(size_t)rowB * (DD * OO) + t * OO + 1] = p11 + q.w + c1;
        }
    }
}

extern "C" void kernel_launch(void* const* d_in, const int* in_sizes, int n_in,
                              void* d_out, int out_size)
{
    const float* x  = (const float*)d_in[0];
    const float* w0 = (const float*)d_in[1];
    const float* w1 = (const float*)d_in[2];
    const float* w2 = (const float*)d_in[3];
    const float* b0 = (const float*)d_in[4];
    const float* b1 = (const float*)d_in[5];
    const float* b2 = (const float*)d_in[6];
    float* out = (float*)d_out;

    const int B = in_sizes[0] / DD;

    cudaFuncSetAttribute(fused_mlp_hmma,
                         cudaFuncAttributeMaxDynamicSharedMemorySize, SMEM_BYTES);

    const int total4 = NX4 + NW04 + NW14;
    prep_kernel<<<(total4 + 255) / 256, 256>>>(x, w0, w1);

    dim3 grid(DD, B / BT);
    fused_mlp_hmma<<<grid, NT, SMEM_BYTES>>>(w2, b0, b1, b2, out);
}

// round 13
// speedup vs baseline: 2.7444x; 1.2062x over previous
#include <cuda_runtime.h>
#include <cuda_fp16.h>
#include <cstdint>

// Fused per-variable MLP, mma.sync m16n8k16 fp16 (all operands fp16, fp32 acc).
// R13: BT=128, warp tile 32 rows x 32 units (nRB=2) -> 2 LDS-u32 per MMA
// (was 3), W staging halves. 2 CTAs/SM.

#define DD 128
#define HH 64
#define OO 2
#define BT 128
#define NT 256
#define SLOPE 0.01f
#define BATCH 8192

#define XS   272
#define W0S  272
#define W1S  144
#define HS   144

#define XT_BYTES  (BT*XS)      // 34816
#define W0T_BYTES (HH*W0S)     // 17408
#define W1T_BYTES (HH*W1S)     // 9216

__device__ __align__(16) unsigned char gX[BATCH*XS];
__device__ __align__(16) unsigned char gW0[DD*W0T_BYTES];
__device__ __align__(16) unsigned char gW1[DD*W1T_BYTES];

// smem byte offsets
#define SM_X   0         // 34816 ; pair p's H window = SM_X + p*8704 (4608 used)
#define SM_W0  34816     // 17408
#define SM_W1  52224     // 9216
#define SM_B0  61440
#define SM_B1  61696
#define SM_W2  61952     // 512
#define SM_P   62464     // 1024
#define SMEM_BYTES 63488

static __device__ __forceinline__ void mma_f16(float acc[4], const uint32_t a[4],
                                               uint32_t b0, uint32_t b1) {
    asm volatile(
        "mma.sync.aligned.m16n8k16.row.col.f32.f16.f16.f32 "
        "{%0,%1,%2,%3}, {%4,%5,%6,%7}, {%8,%9}, {%0,%1,%2,%3};"
        : "+f"(acc[0]), "+f"(acc[1]), "+f"(acc[2]), "+f"(acc[3])
        : "r"(a[0]), "r"(a[1]), "r"(a[2]), "r"(a[3]), "r"(b0), "r"(b1));
}
static __device__ __forceinline__ uint32_t packh2(float a, float b) {
    __half2 h2 = __halves2half2(__float2half_rn(a), __float2half_rn(b));
    return *reinterpret_cast<uint32_t*>(&h2);
}
#define CP16(sdst, gsrc) asm volatile( \
    "cp.async.cg.shared.global [%0], [%1], 16;" :: "r"(sdst), "l"(gsrc))

// ===================== prep =====================
#define NX4  (BATCH*DD/4)
#define NW04 (DD*HH*DD/4)
#define NW14 (DD*HH*HH/4)

__global__ void __launch_bounds__(256)
prep_kernel(const float* __restrict__ x, const float* __restrict__ w0,
            const float* __restrict__ w1)
{
    int idx = blockIdx.x * 256 + threadIdx.x;
    if (idx < NX4) {
        int r = idx >> 5, c = idx & 31;
        float4 v = reinterpret_cast<const float4*>(x)[idx];
        *reinterpret_cast<uint2*>(gX + r * XS + c * 8) =
            make_uint2(packh2(v.x, v.y), packh2(v.z, v.w));
    } else if (idx < NX4 + NW04) {
        int j = idx - NX4;
        int t = j >> 11, k = j & 2047;
        int i = k >> 5, c4 = k & 31;
        float4 v = reinterpret_cast<const float4*>(w0)[j];
        if (c4 == (t >> 2)) reinterpret_cast<float*>(&v)[t & 3] = 0.0f;
        *reinterpret_cast<uint2*>(gW0 + t * W0T_BYTES + i * W0S + c4 * 8) =
            make_uint2(packh2(v.x, v.y), packh2(v.z, v.w));
    } else if (idx < NX4 + NW04 + NW14) {
        int j = idx - NX4 - NW04;
        int t = j >> 10, k = j & 1023;
        int i = k >> 4, c4 = k & 15;
        float4 v = reinterpret_cast<const float4*>(w1)[j];
        *reinterpret_cast<uint2*>(gW1 + t * W1T_BYTES + i * W1S + c4 * 8) =
            make_uint2(packh2(v.x, v.y), packh2(v.z, v.w));
    }
}

// ===================== main =====================
__global__ void __launch_bounds__(NT, 2)
fused_mlp_hmma(const float* __restrict__ w2, const float* __restrict__ b0,
               const float* __restrict__ b1, const float* __restrict__ b2,
               float* __restrict__ out)
{
    extern __shared__ char smem[];
    const int t = blockIdx.x, brow0 = blockIdx.y * BT;
    const int tid = threadIdx.x, wid = tid >> 5, lid = tid & 31;
    const int gid = lid >> 2, tid4 = lid & 3;
    const int pair = wid & 3;           // row group: 32 rows
    const int r0 = pair * 32;
    const int uh = wid >> 2;            // unit half
    const int barid = 1 + pair;

    uint32_t sb;
    asm("{ .reg .u64 tt; cvta.to.shared.u64 tt, %1; cvt.u32.u64 %0, tt; }"
        : "=r"(sb) : "l"(smem));

    // ---- staging ----
    {
        const unsigned char* xp = gX + (size_t)brow0 * XS;
        const unsigned char* w0p = gW0 + (size_t)t * W0T_BYTES;
        const unsigned char* w1p = gW1 + (size_t)t * W1T_BYTES;
        #pragma unroll
        for (int i = tid; i < XT_BYTES / 16; i += NT)
            CP16(sb + SM_X + i * 16, xp + i * 16);
        #pragma unroll
        for (int i = tid; i < W0T_BYTES / 16; i += NT)
            CP16(sb + SM_W0 + i * 16, w0p + i * 16);
        #pragma unroll
        for (int i = tid; i < W1T_BYTES / 16; i += NT)
            CP16(sb + SM_W1 + i * 16, w1p + i * 16);
        asm volatile("cp.async.commit_group;" ::: "memory");
    }
    if (tid < HH) {
        reinterpret_cast<float*>(smem + SM_B0)[tid] = b0[t * HH + tid];
        reinterpret_cast<float*>(smem + SM_B1)[tid] = b1[t * HH + tid];
    }
    if (tid < OO * HH)
        reinterpret_cast<float*>(smem + SM_W2)[tid] = w2[(size_t)t * OO * HH + tid];
    asm volatile("cp.async.wait_group 0;" ::: "memory");
    __syncthreads();

    const float* B0f = reinterpret_cast<const float*>(smem + SM_B0);
    const float* B1f = reinterpret_cast<const float*>(smem + SM_B1);
    const float* W2f = reinterpret_cast<const float*>(smem + SM_W2);

    // per-pair H window aliased over this pair's own (dead) X rows
    char* Hh = smem + SM_X + pair * 8704;

    // ============================ LAYER 0 ============================
    float acc[2][4][4];
    #pragma unroll
    for (int rb = 0; rb < 2; rb++)
        #pragma unroll
        for (int ut = 0; ut < 4; ut++)
            #pragma unroll
            for (int c = 0; c < 4; c++) acc[rb][ut][c] = 0.f;
    {
        const char* XA = smem + SM_X + (r0 + gid) * XS + tid4 * 4;
        const char* WR = smem + SM_W0 + (uh * 32 + gid) * W0S + tid4 * 4;
        #pragma unroll
        for (int ks = 0; ks < 8; ks++) {
            uint32_t xa[2][4];
            #pragma unroll
            for (int rb = 0; rb < 2; rb++) {
                const char* bp = XA + rb * 16 * XS + ks * 32;
                xa[rb][0] = *reinterpret_cast<const uint32_t*>(bp);
                xa[rb][1] = *reinterpret_cast<const uint32_t*>(bp + 8 * XS);
                xa[rb][2] = *reinterpret_cast<const uint32_t*>(bp + 16);
                xa[rb][3] = *reinterpret_cast<const uint32_t*>(bp + 8 * XS + 16);
            }
            #pragma unroll
            for (int ut = 0; ut < 4; ut++) {
                uint32_t bw0 = *reinterpret_cast<const uint32_t*>(WR + ut * 8 * W0S + ks * 32);
                uint32_t bw1 = *reinterpret_cast<const uint32_t*>(WR + ut * 8 * W0S + ks * 32 + 16);
                mma_f16(acc[0][ut], xa[0], bw0, bw1);
                mma_f16(acc[1][ut], xa[1], bw0, bw1);
            }
        }
    }
    // pair must finish reading X before H overwrites its window
    asm volatile("bar.sync %0, 64;" :: "r"(barid) : "memory");
    #pragma unroll
    for (int rb = 0; rb < 2; rb++) {
        #pragma unroll
        for (int ut = 0; ut < 4; ut++) {
            const int un = uh * 32 + ut * 8 + 2 * tid4;
            const float bA = B0f[un], bB = B0f[un + 1];
            float v0 = acc[rb][ut][0] + bA, v1 = acc[rb][ut][1] + bB;
            float v2 = acc[rb][ut][2] + bA, v3 = acc[rb][ut][3] + bB;
            v0 = (v0 > 0.f) ? v0 : SLOPE * v0;
            v1 = (v1 > 0.f) ? v1 : SLOPE * v1;
            v2 = (v2 > 0.f) ? v2 : SLOPE * v2;
            v3 = (v3 > 0.f) ? v3 : SLOPE * v3;
            const int ra = (rb * 16 + gid) * HS + un * 2, rbo = ra + 8 * HS;
            *reinterpret_cast<uint32_t*>(Hh + ra)  = packh2(v0, v1);
            *reinterpret_cast<uint32_t*>(Hh + rbo) = packh2(v2, v3);
        }
    }
    asm volatile("bar.sync %0, 64;" :: "r"(barid) : "memory");

    // ============================ LAYER 1 ============================
    float h1v[2][4][4];
    #pragma unroll
    for (int rb = 0; rb < 2; rb++)
        #pragma unroll
        for (int ut = 0; ut < 4; ut++)
            #pragma unroll
            for (int c = 0; c < 4; c++) h1v[rb][ut][c] = 0.f;
    {
        const char* AH = Hh + gid * HS + tid4 * 4;
        const char* WR = smem + SM_W1 + (uh * 32 + gid) * W1S + tid4 * 4;
        #pragma unroll
        for (int ks = 0; ks < 4; ks++) {
            uint32_t ah[2][4];
            #pragma unroll
            for (int rb = 0; rb < 2; rb++) {
                const char* bp = AH + rb * 16 * HS + ks * 32;
                ah[rb][0] = *reinterpret_cast<const uint32_t*>(bp);
                ah[rb][1] = *reinterpret_cast<const uint32_t*>(bp + 8 * HS);
                ah[rb][2] = *reinterpret_cast<const uint32_t*>(bp + 16);
                ah[rb][3] = *reinterpret_cast<const uint32_t*>(bp + 8 * HS + 16);
            }
            #pragma unroll
            for (int ut = 0; ut < 4; ut++) {
                uint32_t bw0 = *reinterpret_cast<const uint32_t*>(WR + ut * 8 * W1S + ks * 32);
                uint32_t bw1 = *reinterpret_cast<const uint32_t*>(WR + ut * 8 * W1S + ks * 32 + 16);
                mma_f16(h1v[0][ut], ah[0], bw0, bw1);
                mma_f16(h1v[1][ut], ah[1], bw0, bw1);
            }
        }
    }
    #pragma unroll
    for (int rb = 0; rb < 2; rb++)
        #pragma unroll
        for (int ut = 0; ut < 4; ut++) {
            const int un = uh * 32 + ut * 8 + 2 * tid4;
            const float bA = B1f[un], bB = B1f[un + 1];
            float v0 = h1v[rb][ut][0] + bA, v1 = h1v[rb][ut][1] + bB;
            float v2 = h1v[rb][ut][2] + bA, v3 = h1v[rb][ut][3] + bB;
            h1v[rb][ut][0] = (v0 > 0.f) ? v0 : SLOPE * v0;
            h1v[rb][ut][1] = (v1 > 0.f) ? v1 : SLOPE * v1;
            h1v[rb][ut][2] = (v2 > 0.f) ? v2 : SLOPE * v2;
            h1v[rb][ut][3] = (v3 > 0.f) ? v3 : SLOPE * v3;
        }

    // ============================ LAYER 2 ============================
    {
        float p[2][4];
        #pragma unroll
        for (int rb = 0; rb < 2; rb++) {
            p[rb][0] = p[rb][1] = p[rb][2] = p[rb][3] = 0.f;
            #pragma unroll
            for (int ut = 0; ut < 4; ut++) {
                const int u = uh * 32 + ut * 8 + 2 * tid4;
                float2 w2o0 = *reinterpret_cast<const float2*>(W2f + u);
                float2 w2o1 = *reinterpret_cast<const float2*>(W2f + 64 + u);
                p[rb][0] += h1v[rb][ut][0] * w2o0.x + h1v[rb][ut][1] * w2o0.y;
                p[rb][1] += h1v[rb][ut][0] * w2o1.x + h1v[rb][ut][1] * w2o1.y;
                p[rb][2] += h1v[rb][ut][2] * w2o0.x + h1v[rb][ut][3] * w2o0.y;
                p[rb][3] += h1v[rb][ut][2] * w2o1.x + h1v[rb][ut][3] * w2o1.y;
            }
            #pragma unroll
            for (int d = 1; d <= 2; d <<= 1) {
                p[rb][0] += __shfl_xor_sync(0xffffffffu, p[rb][0], d);
                p[rb][1] += __shfl_xor_sync(0xffffffffu, p[rb][1], d);
                p[rb][2] += __shfl_xor_sync(0xffffffffu, p[rb][2], d);
                p[rb][3] += __shfl_xor_sync(0xffffffffu, p[rb][3], d);
            }
        }
        float4* P = reinterpret_cast<float4*>(smem + SM_P);
        if (uh == 1 && tid4 == 0) {
            P[pair * 16 + gid]     = make_float4(p[0][0], p[0][1], p[0][2], p[0][3]);
            P[pair * 16 + 8 + gid] = make_float4(p[1][0], p[1][1], p[1][2], p[1][3]);
        }
        asm volatile("bar.sync %0, 64;" :: "r"(barid) : "memory");
        if (uh == 0 && tid4 == 0) {
            const float c0 = b2[t * OO], c1 = b2[t * OO + 1];
            #pragma unroll
            for (int rb = 0; rb < 2; rb++) {
                float4 q = P[pair * 16 + rb * 8 + gid];
                const int rowA = brow0 + r0 + rb * 16 + gid, rowB = rowA + 8;
                out[(size_t)rowA * (DD * OO) + t * OO]     = p[rb][0] + q.x + c0;
                out[(size_t)rowA * (DD * OO) + t * OO + 1] = p[rb][1] + q.y + c1;
                out[(size_t)rowB * (DD * OO) + t * OO]     = p[rb][2] + q.z + c0;
                out[(size_t)rowB * (DD * OO) + t * OO + 1] = p[rb][3] + q.w + c1;
            }
        }
    }
}

extern "C" void kernel_launch(void* const* d_in, const int* in_sizes, int n_in,
                              void* d_out, int out_size)
{
    const float* x  = (const float*)d_in[0];
    const float* w0 = (const float*)d_in[1];
    const float* w1 = (const float*)d_in[2];
    const float* w2 = (const float*)d_in[3];
    const float* b0 = (const float*)d_in[4];
    const float* b1 = (const float*)d_in[5];
    const float* b2 = (const float*)d_in[6];
    float* out = (float*)d_out;

    const int B = in_sizes[0] / DD;

    cudaFuncSetAttribute(fused_mlp_hmma,
                         cudaFuncAttributeMaxDynamicSharedMemorySize, SMEM_BYTES);

    const int total4 = NX4 + NW04 + NW14;
    prep_kernel<<<(total4 + 255) / 256, 256>>>(x, w0, w1);

    dim3 grid(DD, B / BT);
    fused_mlp_hmma<<<grid, NT, SMEM_BYTES>>>(w2, b0, b1, b2, out);
}

// round 14
// speedup vs baseline: 2.8836x; 1.0507x over previous
#include <cuda_runtime.h>
#include <cuda_fp16.h>
#include <cstdint>

// Fused per-variable MLP, mma.sync m16n8k16 fp16 (all fp16 operands, fp32 acc).
// R14: 2 batch tiles per CTA; W staged once; X tile1 double-buffered via
// cp.async issued before tile0 compute. Warp tile 32 rows x 32 units.

#define DD 128
#define HH 64
#define OO 2
#define BT 128          // rows per tile (2 tiles per CTA)
#define NT 256
#define SLOPE 0.01f
#define BATCH 8192

#define XS   272
#define W0S  272
#define W1S  144
#define HS   144

#define XT_BYTES  (BT*XS)      // 34816
#define W0T_BYTES (HH*W0S)     // 17408
#define W1T_BYTES (HH*W1S)     // 9216

__device__ __align__(16) unsigned char gX[BATCH*XS];
__device__ __align__(16) unsigned char gW0[DD*W0T_BYTES];
__device__ __align__(16) unsigned char gW1[DD*W1T_BYTES];

// smem byte offsets
#define SM_X0  0          // 34816 ; tile0 H windows alias here (pair p: +p*8704)
#define SM_X1  34816      // 34816 ; tile1 H windows alias here
#define SM_W0  69632      // 17408
#define SM_W1  87040      // 9216
#define SM_B0  96256
#define SM_B1  96512
#define SM_W2  96768      // 512
#define SM_P   97280      // 1024
#define SMEM_BYTES 98304

static __device__ __forceinline__ void mma_f16(float acc[4], const uint32_t a[4],
                                               uint32_t b0, uint32_t b1) {
    asm volatile(
        "mma.sync.aligned.m16n8k16.row.col.f32.f16.f16.f32 "
        "{%0,%1,%2,%3}, {%4,%5,%6,%7}, {%8,%9}, {%0,%1,%2,%3};"
        : "+f"(acc[0]), "+f"(acc[1]), "+f"(acc[2]), "+f"(acc[3])
        : "r"(a[0]), "r"(a[1]), "r"(a[2]), "r"(a[3]), "r"(b0), "r"(b1));
}
static __device__ __forceinline__ uint32_t packh2(float a, float b) {
    __half2 h2 = __halves2half2(__float2half_rn(a), __float2half_rn(b));
    return *reinterpret_cast<uint32_t*>(&h2);
}
#define CP16(sdst, gsrc) asm volatile( \
    "cp.async.cg.shared.global [%0], [%1], 16;" :: "r"(sdst), "l"(gsrc))

// ===================== prep =====================
#define NX4  (BATCH*DD/4)
#define NW04 (DD*HH*DD/4)
#define NW14 (DD*HH*HH/4)

__global__ void __launch_bounds__(256)
prep_kernel(const float* __restrict__ x, const float* __restrict__ w0,
            const float* __restrict__ w1)
{
    int idx = blockIdx.x * 256 + threadIdx.x;
    if (idx < NX4) {
        int r = idx >> 5, c = idx & 31;
        float4 v = reinterpret_cast<const float4*>(x)[idx];
        *reinterpret_cast<uint2*>(gX + r * XS + c * 8) =
            make_uint2(packh2(v.x, v.y), packh2(v.z, v.w));
    } else if (idx < NX4 + NW04) {
        int j = idx - NX4;
        int t = j >> 11, k = j & 2047;
        int i = k >> 5, c4 = k & 31;
        float4 v = reinterpret_cast<const float4*>(w0)[j];
        if (c4 == (t >> 2)) reinterpret_cast<float*>(&v)[t & 3] = 0.0f;
        *reinterpret_cast<uint2*>(gW0 + t * W0T_BYTES + i * W0S + c4 * 8) =
            make_uint2(packh2(v.x, v.y), packh2(v.z, v.w));
    } else if (idx < NX4 + NW04 + NW14) {
        int j = idx - NX4 - NW04;
        int t = j >> 10, k = j & 1023;
        int i = k >> 4, c4 = k & 15;
        float4 v = reinterpret_cast<const float4*>(w1)[j];
        *reinterpret_cast<uint2*>(gW1 + t * W1T_BYTES + i * W1S + c4 * 8) =
            make_uint2(packh2(v.x, v.y), packh2(v.z, v.w));
    }
}

// ===================== main =====================
__global__ void __launch_bounds__(NT, 2)
fused_mlp_hmma(const float* __restrict__ w2, const float* __restrict__ b0,
               const float* __restrict__ b1, const float* __restrict__ b2,
               float* __restrict__ out)
{
    extern __shared__ char smem[];
    const int t = blockIdx.x, brow00 = blockIdx.y * (2 * BT);
    const int tid = threadIdx.x, wid = tid >> 5, lid = tid & 31;
    const int gid = lid >> 2, tid4 = lid & 3;
    const int pair = wid & 3;           // row group (32 rows)
    const int r0 = pair * 32;
    const int uh = wid >> 2;            // unit half
    const int barid = 1 + pair;

    uint32_t sb;
    asm("{ .reg .u64 tt; cvta.to.shared.u64 tt, %1; cvt.u32.u64 %0, tt; }"
        : "=r"(sb) : "l"(smem));

    // ---- stage tile0 X + W0 + W1 ----
    {
        const unsigned char* xp = gX + (size_t)brow00 * XS;
        const unsigned char* w0p = gW0 + (size_t)t * W0T_BYTES;
        const unsigned char* w1p = gW1 + (size_t)t * W1T_BYTES;
        #pragma unroll
        for (int i = tid; i < XT_BYTES / 16; i += NT)
            CP16(sb + SM_X0 + i * 16, xp + i * 16);
        #pragma unroll
        for (int i = tid; i < W0T_BYTES / 16; i += NT)
            CP16(sb + SM_W0 + i * 16, w0p + i * 16);
        #pragma unroll
        for (int i = tid; i < W1T_BYTES / 16; i += NT)
            CP16(sb + SM_W1 + i * 16, w1p + i * 16);
        asm volatile("cp.async.commit_group;" ::: "memory");
    }
    if (tid < HH) {
        reinterpret_cast<float*>(smem + SM_B0)[tid] = b0[t * HH + tid];
        reinterpret_cast<float*>(smem + SM_B1)[tid] = b1[t * HH + tid];
    }
    if (tid < OO * HH)
        reinterpret_cast<float*>(smem + SM_W2)[tid] = w2[(size_t)t * OO * HH + tid];
    asm volatile("cp.async.wait_group 0;" ::: "memory");
    __syncthreads();

    // ---- prefetch tile1 X (hides behind tile0 compute) ----
    {
        const unsigned char* xp = gX + (size_t)(brow00 + BT) * XS;
        #pragma unroll
        for (int i = tid; i < XT_BYTES / 16; i += NT)
            CP16(sb + SM_X1 + i * 16, xp + i * 16);
        asm volatile("cp.async.commit_group;" ::: "memory");
    }

    const float* B0f = reinterpret_cast<const float*>(smem + SM_B0);
    const float* B1f = reinterpret_cast<const float*>(smem + SM_B1);
    const float* W2f = reinterpret_cast<const float*>(smem + SM_W2);
    const float c0 = b2[t * OO], c1 = b2[t * OO + 1];

    for (int tile = 0; tile < 2; tile++) {
        const int xbase = tile ? SM_X1 : SM_X0;
        const int brow0 = brow00 + tile * BT;
        if (tile == 1) {
            asm volatile("cp.async.wait_group 0;" ::: "memory");
            __syncthreads();
        }
        char* Hh = smem + xbase + pair * 8704;   // H aliases this tile's dead X rows

        // ===================== LAYER 0 =====================
        float acc[2][4][4];
        #pragma unroll
        for (int rb = 0; rb < 2; rb++)
            #pragma unroll
            for (int ut = 0; ut < 4; ut++)
                #pragma unroll
                for (int c = 0; c < 4; c++) acc[rb][ut][c] = 0.f;
        {
            const char* XA = smem + xbase + (r0 + gid) * XS + tid4 * 4;
            const char* WR = smem + SM_W0 + (uh * 32 + gid) * W0S + tid4 * 4;
            #pragma unroll
            for (int ks = 0; ks < 8; ks++) {
                uint32_t xa[2][4];
                #pragma unroll
                for (int rb = 0; rb < 2; rb++) {
                    const char* bp = XA + rb * 16 * XS + ks * 32;
                    xa[rb][0] = *reinterpret_cast<const uint32_t*>(bp);
                    xa[rb][1] = *reinterpret_cast<const uint32_t*>(bp + 8 * XS);
                    xa[rb][2] = *reinterpret_cast<const uint32_t*>(bp + 16);
                    xa[rb][3] = *reinterpret_cast<const uint32_t*>(bp + 8 * XS + 16);
                }
                #pragma unroll
                for (int ut = 0; ut < 4; ut++) {
                    uint32_t bw0 = *reinterpret_cast<const uint32_t*>(WR + ut * 8 * W0S + ks * 32);
                    uint32_t bw1 = *reinterpret_cast<const uint32_t*>(WR + ut * 8 * W0S + ks * 32 + 16);
                    mma_f16(acc[0][ut], xa[0], bw0, bw1);
                    mma_f16(acc[1][ut], xa[1], bw0, bw1);
                }
            }
        }
        asm volatile("bar.sync %0, 64;" :: "r"(barid) : "memory");
        #pragma unroll
        for (int rb = 0; rb < 2; rb++) {
            #pragma unroll
            for (int ut = 0; ut < 4; ut++) {
                const int un = uh * 32 + ut * 8 + 2 * tid4;
                const float bA = B0f[un], bB = B0f[un + 1];
                float v0 = acc[rb][ut][0] + bA, v1 = acc[rb][ut][1] + bB;
                float v2 = acc[rb][ut][2] + bA, v3 = acc[rb][ut][3] + bB;
                v0 = (v0 > 0.f) ? v0 : SLOPE * v0;
                v1 = (v1 > 0.f) ? v1 : SLOPE * v1;
                v2 = (v2 > 0.f) ? v2 : SLOPE * v2;
                v3 = (v3 > 0.f) ? v3 : SLOPE * v3;
                const int ra = (rb * 16 + gid) * HS + un * 2, rbo = ra + 8 * HS;
                *reinterpret_cast<uint32_t*>(Hh + ra)  = packh2(v0, v1);
                *reinterpret_cast<uint32_t*>(Hh + rbo) = packh2(v2, v3);
            }
        }
        asm volatile("bar.sync %0, 64;" :: "r"(barid) : "memory");

        // ===================== LAYER 1 =====================
        float h1v[2][4][4];
        #pragma unroll
        for (int rb = 0; rb < 2; rb++)
            #pragma unroll
            for (int ut = 0; ut < 4; ut++)
                #pragma unroll
                for (int c = 0; c < 4; c++) h1v[rb][ut][c] = 0.f;
        {
            const char* AH = Hh + gid * HS + tid4 * 4;
            const char* WR = smem + SM_W1 + (uh * 32 + gid) * W1S + tid4 * 4;
            #pragma unroll
            for (int ks = 0; ks < 4; ks++) {
                uint32_t ah[2][4];
                #pragma unroll
                for (int rb = 0; rb < 2; rb++) {
                    const char* bp = AH + rb * 16 * HS + ks * 32;
                    ah[rb][0] = *reinterpret_cast<const uint32_t*>(bp);
                    ah[rb][1] = *reinterpret_cast<const uint32_t*>(bp + 8 * HS);
                    ah[rb][2] = *reinterpret_cast<const uint32_t*>(bp + 16);
                    ah[rb][3] = *reinterpret_cast<const uint32_t*>(bp + 8 * HS + 16);
                }
                #pragma unroll
                for (int ut = 0; ut < 4; ut++) {
                    uint32_t bw0 = *reinterpret_cast<const uint32_t*>(WR + ut * 8 * W1S + ks * 32);
                    uint32_t bw1 = *reinterpret_cast<const uint32_t*>(WR + ut * 8 * W1S + ks * 32 + 16);
                    mma_f16(h1v[0][ut], ah[0], bw0, bw1);
                    mma_f16(h1v[1][ut], ah[1], bw0, bw1);
                }
            }
        }
        #pragma unroll
        for (int rb = 0; rb < 2; rb++)
            #pragma unroll
            for (int ut = 0; ut < 4; ut++) {
                const int un = uh * 32 + ut * 8 + 2 * tid4;
                const float bA = B1f[un], bB = B1f[un + 1];
                float v0 = h1v[rb][ut][0] + bA, v1 = h1v[rb][ut][1] + bB;
                float v2 = h1v[rb][ut][2] + bA, v3 = h1v[rb][ut][3] + bB;
                h1v[rb][ut][0] = (v0 > 0.f) ? v0 : SLOPE * v0;
                h1v[rb][ut][1] = (v1 > 0.f) ? v1 : SLOPE * v1;
                h1v[rb][ut][2] = (v2 > 0.f) ? v2 : SLOPE * v2;
                h1v[rb][ut][3] = (v3 > 0.f) ? v3 : SLOPE * v3;
            }

        // ===================== LAYER 2 =====================
        {
            float p[2][4];
            #pragma unroll
            for (int rb = 0; rb < 2; rb++) {
                p[rb][0] = p[rb][1] = p[rb][2] = p[rb][3] = 0.f;
                #pragma unroll
                for (int ut = 0; ut < 4; ut++) {
                    const int u = uh * 32 + ut * 8 + 2 * tid4;
                    float2 w2o0 = *reinterpret_cast<const float2*>(W2f + u);
                    float2 w2o1 = *reinterpret_cast<const float2*>(W2f + 64 + u);
                    p[rb][0] += h1v[rb][ut][0] * w2o0.x + h1v[rb][ut][1] * w2o0.y;
                    p[rb][1] += h1v[rb][ut][0] * w2o1.x + h1v[rb][ut][1] * w2o1.y;
                    p[rb][2] += h1v[rb][ut][2] * w2o0.x + h1v[rb][ut][3] * w2o0.y;
                    p[rb][3] += h1v[rb][ut][2] * w2o1.x + h1v[rb][ut][3] * w2o1.y;
                }
                #pragma unroll
                for (int d = 1; d <= 2; d <<= 1) {
                    p[rb][0] += __shfl_xor_sync(0xffffffffu, p[rb][0], d);
                    p[rb][1] += __shfl_xor_sync(0xffffffffu, p[rb][1], d);
                    p[rb][2] += __shfl_xor_sync(0xffffffffu, p[rb][2], d);
                    p[rb][3] += __shfl_xor_sync(0xffffffffu, p[rb][3], d);
                }
            }
            float4* P = reinterpret_cast<float4*>(smem + SM_P);
            if (uh == 1 && tid4 == 0) {
                P[pair * 16 + gid]     = make_float4(p[0][0], p[0][1], p[0][2], p[0][3]);
                P[pair * 16 + 8 + gid] = make_float4(p[1][0], p[1][1], p[1][2], p[1][3]);
            }
            asm volatile("bar.sync %0, 64;" :: "r"(barid) : "memory");
            if (uh == 0 && tid4 == 0) {
                #pragma unroll
                for (int rb = 0; rb < 2; rb++) {
                    float4 q = P[pair * 16 + rb * 8 + gid];
                    const int rowA = brow0 + r0 + rb * 16 + gid, rowB = rowA + 8;
                    out[(size_t)rowA * (DD * OO) + t * OO]     = p[rb][0] + q.x + c0;
                    out[(size_t)rowA * (DD * OO) + t * OO + 1] = p[rb][1] + q.y + c1;
                    out[(size_t)rowB * (DD * OO) + t * OO]     = p[rb][2] + q.z + c0;
                    out[(size_t)rowB * (DD * OO) + t * OO + 1] = p[rb][3] + q.w + c1;
                }
            }
        }
        // tile1's first pair barrier orders P reuse across tiles
    }
}

extern "C" void kernel_launch(void* const* d_in, const int* in_sizes, int n_in,
                              void* d_out, int out_size)
{
    const float* x  = (const float*)d_in[0];
    const float* w0 = (const float*)d_in[1];
    const float* w1 = (const float*)d_in[2];
    const float* w2 = (const float*)d_in[3];
    const float* b0 = (const float*)d_in[4];
    const float* b1 = (const float*)d_in[5];
    const float* b2 = (const float*)d_in[6];
    float* out = (float*)d_out;

    const int B = in_sizes[0] / DD;

    cudaFuncSetAttribute(fused_mlp_hmma,
                         cudaFuncAttributeMaxDynamicSharedMemorySize, SMEM_BYTES);

    const int total4 = NX4 + NW04 + NW14;
    prep_kernel<<<(total4 + 255) / 256, 256>>>(x, w0, w1);

    dim3 grid(DD, B / (2 * BT));    // (128, 32)
    fused_mlp_hmma<<<grid, NT, SMEM_BYTES>>>(w2, b0, b1, b2, out);
}

// round 15
// speedup vs baseline: 2.9532x; 1.0241x over previous
#include <cuda_runtime.h>
#include <cuda_fp16.h>
#include <cstdint>

// Fused per-variable MLP, mma.sync m16n8k16 fp16 (all fp16 operands, fp32 acc).
// R15: 4 batch tiles per CTA, ping-pong X buffers with cp.async pipeline
// (exposed staging once per 4 tiles); bias folded into accumulator init.

#define DD 128
#define HH 64
#define OO 2
#define BT 128          // rows per tile (4 tiles per CTA)
#define NTILES 4
#define NT 256
#define SLOPE 0.01f
#define BATCH 8192

#define XS   272
#define W0S  272
#define W1S  144
#define HS   144

#define XT_BYTES  (BT*XS)      // 34816
#define W0T_BYTES (HH*W0S)     // 17408
#define W1T_BYTES (HH*W1S)     // 9216

__device__ __align__(16) unsigned char gX[BATCH*XS];
__device__ __align__(16) unsigned char gW0[DD*W0T_BYTES];
__device__ __align__(16) unsigned char gW1[DD*W1T_BYTES];

// smem byte offsets
#define SM_X0  0          // 34816 ; tiles 0,2 (H windows alias: pair p -> +p*8704)
#define SM_X1  34816      // 34816 ; tiles 1,3
#define SM_W0  69632      // 17408
#define SM_W1  87040      // 9216
#define SM_B0  96256
#define SM_B1  96512
#define SM_W2  96768      // 512
#define SM_P   97280      // 1024
#define SMEM_BYTES 98304

static __device__ __forceinline__ void mma_f16(float acc[4], const uint32_t a[4],
                                               uint32_t b0, uint32_t b1) {
    asm volatile(
        "mma.sync.aligned.m16n8k16.row.col.f32.f16.f16.f32 "
        "{%0,%1,%2,%3}, {%4,%5,%6,%7}, {%8,%9}, {%0,%1,%2,%3};"
        : "+f"(acc[0]), "+f"(acc[1]), "+f"(acc[2]), "+f"(acc[3])
        : "r"(a[0]), "r"(a[1]), "r"(a[2]), "r"(a[3]), "r"(b0), "r"(b1));
}
static __device__ __forceinline__ uint32_t packh2(float a, float b) {
    __half2 h2 = __halves2half2(__float2half_rn(a), __float2half_rn(b));
    return *reinterpret_cast<uint32_t*>(&h2);
}
#define CP16(sdst, gsrc) asm volatile( \
    "cp.async.cg.shared.global [%0], [%1], 16;" :: "r"(sdst), "l"(gsrc))

// ===================== prep =====================
#define NX4  (BATCH*DD/4)
#define NW04 (DD*HH*DD/4)
#define NW14 (DD*HH*HH/4)

__global__ void __launch_bounds__(256)
prep_kernel(const float* __restrict__ x, const float* __restrict__ w0,
            const float* __restrict__ w1)
{
    int idx = blockIdx.x * 256 + threadIdx.x;
    if (idx < NX4) {
        int r = idx >> 5, c = idx & 31;
        float4 v = reinterpret_cast<const float4*>(x)[idx];
        *reinterpret_cast<uint2*>(gX + r * XS + c * 8) =
            make_uint2(packh2(v.x, v.y), packh2(v.z, v.w));
    } else if (idx < NX4 + NW04) {
        int j = idx - NX4;
        int t = j >> 11, k = j & 2047;
        int i = k >> 5, c4 = k & 31;
        float4 v = reinterpret_cast<const float4*>(w0)[j];
        if (c4 == (t >> 2)) reinterpret_cast<float*>(&v)[t & 3] = 0.0f;
        *reinterpret_cast<uint2*>(gW0 + t * W0T_BYTES + i * W0S + c4 * 8) =
            make_uint2(packh2(v.x, v.y), packh2(v.z, v.w));
    } else if (idx < NX4 + NW04 + NW14) {
        int j = idx - NX4 - NW04;
        int t = j >> 10, k = j & 1023;
        int i = k >> 4, c4 = k & 15;
        float4 v = reinterpret_cast<const float4*>(w1)[j];
        *reinterpret_cast<uint2*>(gW1 + t * W1T_BYTES + i * W1S + c4 * 8) =
            make_uint2(packh2(v.x, v.y), packh2(v.z, v.w));
    }
}

// ===================== main =====================
__global__ void __launch_bounds__(NT, 2)
fused_mlp_hmma(const float* __restrict__ w2, const float* __restrict__ b0,
               const float* __restrict__ b1, const float* __restrict__ b2,
               float* __restrict__ out)
{
    extern __shared__ char smem[];
    const int t = blockIdx.x, brow00 = blockIdx.y * (NTILES * BT);
    const int tid = threadIdx.x, wid = tid >> 5, lid = tid & 31;
    const int gid = lid >> 2, tid4 = lid & 3;
    const int pair = wid & 3;           // row group (32 rows)
    const int r0 = pair * 32;
    const int uh = wid >> 2;            // unit half
    const int barid = 1 + pair;

    uint32_t sb;
    asm("{ .reg .u64 tt; cvta.to.shared.u64 tt, %1; cvt.u32.u64 %0, tt; }"
        : "=r"(sb) : "l"(smem));

    // ---- group 0: X(0) + W0 + W1 ----
    {
        const unsigned char* xp = gX + (size_t)brow00 * XS;
        const unsigned char* w0p = gW0 + (size_t)t * W0T_BYTES;
        const unsigned char* w1p = gW1 + (size_t)t * W1T_BYTES;
        #pragma unroll
        for (int i = tid; i < XT_BYTES / 16; i += NT)
            CP16(sb + SM_X0 + i * 16, xp + i * 16);
        #pragma unroll
        for (int i = tid; i < W0T_BYTES / 16; i += NT)
            CP16(sb + SM_W0 + i * 16, w0p + i * 16);
        #pragma unroll
        for (int i = tid; i < W1T_BYTES / 16; i += NT)
            CP16(sb + SM_W1 + i * 16, w1p + i * 16);
        asm volatile("cp.async.commit_group;" ::: "memory");
    }
    // ---- group 1: X(1) ----
    {
        const unsigned char* xp = gX + (size_t)(brow00 + BT) * XS;
        #pragma unroll
        for (int i = tid; i < XT_BYTES / 16; i += NT)
            CP16(sb + SM_X1 + i * 16, xp + i * 16);
        asm volatile("cp.async.commit_group;" ::: "memory");
    }
    if (tid < HH) {
        reinterpret_cast<float*>(smem + SM_B0)[tid] = b0[t * HH + tid];
        reinterpret_cast<float*>(smem + SM_B1)[tid] = b1[t * HH + tid];
    }
    if (tid < OO * HH)
        reinterpret_cast<float*>(smem + SM_W2)[tid] = w2[(size_t)t * OO * HH + tid];
    asm volatile("cp.async.wait_group 1;" ::: "memory");   // group 0 done
    __syncthreads();

    const float* B0f = reinterpret_cast<const float*>(smem + SM_B0);
    const float* B1f = reinterpret_cast<const float*>(smem + SM_B1);
    const float* W2f = reinterpret_cast<const float*>(smem + SM_W2);
    const float c0 = b2[t * OO], c1 = b2[t * OO + 1];

    #pragma unroll 1
    for (int tile = 0; tile < NTILES; tile++) {
        const int xbase = (tile & 1) ? SM_X1 : SM_X0;
        const int brow0 = brow00 + tile * BT;
        char* Hh = smem + xbase + pair * 8704;   // H aliases this tile's dead X rows

        // ===================== LAYER 0 (acc init = bias) =====================
        float acc[2][4][4];
        #pragma unroll
        for (int ut = 0; ut < 4; ut++) {
            const int un = uh * 32 + ut * 8 + 2 * tid4;
            const float bA = B0f[un], bB = B0f[un + 1];
            acc[0][ut][0] = bA; acc[0][ut][1] = bB; acc[0][ut][2] = bA; acc[0][ut][3] = bB;
            acc[1][ut][0] = bA; acc[1][ut][1] = bB; acc[1][ut][2] = bA; acc[1][ut][3] = bB;
        }
        {
            const char* XA = smem + xbase + (r0 + gid) * XS + tid4 * 4;
            const char* WR = smem + SM_W0 + (uh * 32 + gid) * W0S + tid4 * 4;
            #pragma unroll
            for (int ks = 0; ks < 8; ks++) {
                uint32_t xa[2][4];
                #pragma unroll
                for (int rb = 0; rb < 2; rb++) {
                    const char* bp = XA + rb * 16 * XS + ks * 32;
                    xa[rb][0] = *reinterpret_cast<const uint32_t*>(bp);
                    xa[rb][1] = *reinterpret_cast<const uint32_t*>(bp + 8 * XS);
                    xa[rb][2] = *reinterpret_cast<const uint32_t*>(bp + 16);
                    xa[rb][3] = *reinterpret_cast<const uint32_t*>(bp + 8 * XS + 16);
                }
                #pragma unroll
                for (int ut = 0; ut < 4; ut++) {
                    uint32_t bw0 = *reinterpret_cast<const uint32_t*>(WR + ut * 8 * W0S + ks * 32);
                    uint32_t bw1 = *reinterpret_cast<const uint32_t*>(WR + ut * 8 * W0S + ks * 32 + 16);
                    mma_f16(acc[0][ut], xa[0], bw0, bw1);
                    mma_f16(acc[1][ut], xa[1], bw0, bw1);
                }
            }
        }
        asm volatile("bar.sync %0, 64;" :: "r"(barid) : "memory");
        #pragma unroll
        for (int rb = 0; rb < 2; rb++) {
            #pragma unroll
            for (int ut = 0; ut < 4; ut++) {
                const int un = uh * 32 + ut * 8 + 2 * tid4;
                float v0 = acc[rb][ut][0], v1 = acc[rb][ut][1];
                float v2 = acc[rb][ut][2], v3 = acc[rb][ut][3];
                v0 = fmaxf(v0, SLOPE * v0);
                v1 = fmaxf(v1, SLOPE * v1);
                v2 = fmaxf(v2, SLOPE * v2);
                v3 = fmaxf(v3, SLOPE * v3);
                const int ra = (rb * 16 + gid) * HS + un * 2, rbo = ra + 8 * HS;
                *reinterpret_cast<uint32_t*>(Hh + ra)  = packh2(v0, v1);
                *reinterpret_cast<uint32_t*>(Hh + rbo) = packh2(v2, v3);
            }
        }
        asm volatile("bar.sync %0, 64;" :: "r"(barid) : "memory");

        // ===================== LAYER 1 (acc init = bias) =====================
        float h1v[2][4][4];
        #pragma unroll
        for (int ut = 0; ut < 4; ut++) {
            const int un = uh * 32 + ut * 8 + 2 * tid4;
            const float bA = B1f[un], bB = B1f[un + 1];
            h1v[0][ut][0] = bA; h1v[0][ut][1] = bB; h1v[0][ut][2] = bA; h1v[0][ut][3] = bB;
            h1v[1][ut][0] = bA; h1v[1][ut][1] = bB; h1v[1][ut][2] = bA; h1v[1][ut][3] = bB;
        }
        {
            const char* AH = Hh + gid * HS + tid4 * 4;
            const char* WR = smem + SM_W1 + (uh * 32 + gid) * W1S + tid4 * 4;
            #pragma unroll
            for (int ks = 0; ks < 4; ks++) {
                uint32_t ah[2][4];
                #pragma unroll
                for (int rb = 0; rb < 2; rb++) {
                    const char* bp = AH + rb * 16 * HS + ks * 32;
                    ah[rb][0] = *reinterpret_cast<const uint32_t*>(bp);
                    ah[rb][1] = *reinterpret_cast<const uint32_t*>(bp + 8 * HS);
                    ah[rb][2] = *reinterpret_cast<const uint32_t*>(bp + 16);
                    ah[rb][3] = *reinterpret_cast<const uint32_t*>(bp + 8 * HS + 16);
                }
                #pragma unroll
                for (int ut = 0; ut < 4; ut++) {
                    uint32_t bw0 = *reinterpret_cast<const uint32_t*>(WR + ut * 8 * W1S + ks * 32);
                    uint32_t bw1 = *reinterpret_cast<const uint32_t*>(WR + ut * 8 * W1S + ks * 32 + 16);
                    mma_f16(h1v[0][ut], ah[0], bw0, bw1);
                    mma_f16(h1v[1][ut], ah[1], bw0, bw1);
                }
            }
        }
        #pragma unroll
        for (int rb = 0; rb < 2; rb++)
            #pragma unroll
            for (int ut = 0; ut < 4; ut++) {
                h1v[rb][ut][0] = fmaxf(h1v[rb][ut][0], SLOPE * h1v[rb][ut][0]);
                h1v[rb][ut][1] = fmaxf(h1v[rb][ut][1], SLOPE * h1v[rb][ut][1]);
                h1v[rb][ut][2] = fmaxf(h1v[rb][ut][2], SLOPE * h1v[rb][ut][2]);
                h1v[rb][ut][3] = fmaxf(h1v[rb][ut][3], SLOPE * h1v[rb][ut][3]);
            }

        // ===================== LAYER 2 =====================
        {
            float p[2][4];
            #pragma unroll
            for (int rb = 0; rb < 2; rb++) {
                p[rb][0] = p[rb][1] = p[rb][2] = p[rb][3] = 0.f;
                #pragma unroll
                for (int ut = 0; ut < 4; ut++) {
                    const int u = uh * 32 + ut * 8 + 2 * tid4;
                    float2 w2o0 = *reinterpret_cast<const float2*>(W2f + u);
                    float2 w2o1 = *reinterpret_cast<const float2*>(W2f + 64 + u);
                    p[rb][0] += h1v[rb][ut][0] * w2o0.x + h1v[rb][ut][1] * w2o0.y;
                    p[rb][1] += h1v[rb][ut][0] * w2o1.x + h1v[rb][ut][1] * w2o1.y;
                    p[rb][2] += h1v[rb][ut][2] * w2o0.x + h1v[rb][ut][3] * w2o0.y;
                    p[rb][3] += h1v[rb][ut][2] * w2o1.x + h1v[rb][ut][3] * w2o1.y;
                }
                #pragma unroll
                for (int d = 1; d <= 2; d <<= 1) {
                    p[rb][0] += __shfl_xor_sync(0xffffffffu, p[rb][0], d);
                    p[rb][1] += __shfl_xor_sync(0xffffffffu, p[rb][1], d);
                    p[rb][2] += __shfl_xor_sync(0xffffffffu, p[rb][2], d);
                    p[rb][3] += __shfl_xor_sync(0xffffffffu, p[rb][3], d);
                }
            }
            float4* P = reinterpret_cast<float4*>(smem + SM_P);
            if (uh == 1 && tid4 == 0) {
                P[pair * 16 + gid]     = make_float4(p[0][0], p[0][1], p[0][2], p[0][3]);
                P[pair * 16 + 8 + gid] = make_float4(p[1][0], p[1][1], p[1][2], p[1][3]);
            }
            asm volatile("bar.sync %0, 64;" :: "r"(barid) : "memory");
            if (uh == 0 && tid4 == 0) {
                #pragma unroll
                for (int rb = 0; rb < 2; rb++) {
                    float4 q = P[pair * 16 + rb * 8 + gid];
                    const int rowA = brow0 + r0 + rb * 16 + gid, rowB = rowA + 8;
                    out[(size_t)rowA * (DD * OO) + t * OO]     = p[rb][0] + q.x + c0;
                    out[(size_t)rowA * (DD * OO) + t * OO + 1] = p[rb][1] + q.y + c1;
                    out[(size_t)rowB * (DD * OO) + t * OO]     = p[rb][2] + q.z + c0;
                    out[(size_t)rowB * (DD * OO) + t * OO + 1] = p[rb][3] + q.w + c1;
                }
            }
        }

        // ---- pipeline: refill this buffer with X(tile+2), arm next tile ----
        if (tile < NTILES - 1) {
            __syncthreads();                    // all reads of this buffer done
            if (tile < NTILES - 2) {
                const unsigned char* xp = gX + (size_t)(brow00 + (tile + 2) * BT) * XS;
                #pragma unroll
                for (int i = tid; i < XT_BYTES / 16; i += NT)
                    CP16(sb + xbase + i * 16, xp + i * 16);
                asm volatile("cp.async.commit_group;" ::: "memory");
                asm volatile("cp.async.wait_group 1;" ::: "memory");  // next tile ready
            } else {
                asm volatile("cp.async.wait_group 0;" ::: "memory");
            }
            __syncthreads();
        }
    }
}

extern "C" void kernel_launch(void* const* d_in, const int* in_sizes, int n_in,
                              void* d_out, int out_size)
{
    const float* x  = (const float*)d_in[0];
    const float* w0 = (const float*)d_in[1];
    const float* w1 = (const float*)d_in[2];
    const float* w2 = (const float*)d_in[3];
    const float* b0 = (const float*)d_in[4];
    const float* b1 = (const float*)d_in[5];
    const float* b2 = (const float*)d_in[6];
    float* out = (float*)d_out;

    const int B = in_sizes[0] / DD;

    cudaFuncSetAttribute(fused_mlp_hmma,
                         cudaFuncAttributeMaxDynamicSharedMemorySize, SMEM_BYTES);

    const int total4 = NX4 + NW04 + NW14;
    prep_kernel<<<(total4 + 255) / 256, 256>>>(x, w0, w1);

    dim3 grid(DD, B / (NTILES * BT));    // (128, 16)
    fused_mlp_hmma<<<grid, NT, SMEM_BYTES>>>(w2, b0, b1, b2, out);
}

// round 16
// speedup vs baseline: 3.1302x; 1.0599x over previous
#include <cuda_runtime.h>
#include <cuda_fp16.h>
#include <cstdint>

// Fused per-variable MLP, mma.sync m16n8k16 fp16 (all fp16 operands, fp32 acc).
// R16: single X buffer (refilled per tile), 4 tiles/CTA for W amortization,
// 63.5 KB smem + <=85 regs -> 3 CTAs/SM. Cross-CTA overlap hides staging.

#define DD 128
#define HH 64
#define OO 2
#define BT 128          // rows per tile (4 tiles per CTA)
#define NTILES 4
#define NT 256
#define SLOPE 0.01f
#define BATCH 8192

#define XS   272
#define W0S  272
#define W1S  144
#define HS   144

#define XT_BYTES  (BT*XS)      // 34816
#define W0T_BYTES (HH*W0S)     // 17408
#define W1T_BYTES (HH*W1S)     // 9216

__device__ __align__(16) unsigned char gX[BATCH*XS];
__device__ __align__(16) unsigned char gW0[DD*W0T_BYTES];
__device__ __align__(16) unsigned char gW1[DD*W1T_BYTES];

// smem byte offsets
#define SM_X   0          // 34816 ; pair p's H window = SM_X + p*8704
#define SM_W0  34816      // 17408
#define SM_W1  52224      // 9216
#define SM_B0  61440
#define SM_B1  61696
#define SM_W2  61952      // 512
#define SM_P   62464      // 1024
#define SMEM_BYTES 63488

static __device__ __forceinline__ void mma_f16(float acc[4], const uint32_t a[4],
                                               uint32_t b0, uint32_t b1) {
    asm volatile(
        "mma.sync.aligned.m16n8k16.row.col.f32.f16.f16.f32 "
        "{%0,%1,%2,%3}, {%4,%5,%6,%7}, {%8,%9}, {%0,%1,%2,%3};"
        : "+f"(acc[0]), "+f"(acc[1]), "+f"(acc[2]), "+f"(acc[3])
        : "r"(a[0]), "r"(a[1]), "r"(a[2]), "r"(a[3]), "r"(b0), "r"(b1));
}
static __device__ __forceinline__ uint32_t packh2(float a, float b) {
    __half2 h2 = __halves2half2(__float2half_rn(a), __float2half_rn(b));
    return *reinterpret_cast<uint32_t*>(&h2);
}
#define CP16(sdst, gsrc) asm volatile( \
    "cp.async.cg.shared.global [%0], [%1], 16;" :: "r"(sdst), "l"(gsrc))

// ===================== prep =====================
#define NX4  (BATCH*DD/4)
#define NW04 (DD*HH*DD/4)
#define NW14 (DD*HH*HH/4)

__global__ void __launch_bounds__(256)
prep_kernel(const float* __restrict__ x, const float* __restrict__ w0,
            const float* __restrict__ w1)
{
    int idx = blockIdx.x * 256 + threadIdx.x;
    if (idx < NX4) {
        int r = idx >> 5, c = idx & 31;
        float4 v = reinterpret_cast<const float4*>(x)[idx];
        *reinterpret_cast<uint2*>(gX + r * XS + c * 8) =
            make_uint2(packh2(v.x, v.y), packh2(v.z, v.w));
    } else if (idx < NX4 + NW04) {
        int j = idx - NX4;
        int t = j >> 11, k = j & 2047;
        int i = k >> 5, c4 = k & 31;
        float4 v = reinterpret_cast<const float4*>(w0)[j];
        if (c4 == (t >> 2)) reinterpret_cast<float*>(&v)[t & 3] = 0.0f;
        *reinterpret_cast<uint2*>(gW0 + t * W0T_BYTES + i * W0S + c4 * 8) =
            make_uint2(packh2(v.x, v.y), packh2(v.z, v.w));
    } else if (idx < NX4 + NW04 + NW14) {
        int j = idx - NX4 - NW04;
        int t = j >> 10, k = j & 1023;
        int i = k >> 4, c4 = k & 15;
        float4 v = reinterpret_cast<const float4*>(w1)[j];
        *reinterpret_cast<uint2*>(gW1 + t * W1T_BYTES + i * W1S + c4 * 8) =
            make_uint2(packh2(v.x, v.y), packh2(v.z, v.w));
    }
}

// ===================== main =====================
__global__ void __launch_bounds__(NT, 3)
fused_mlp_hmma(const float* __restrict__ w2, const float* __restrict__ b0,
               const float* __restrict__ b1, const float* __restrict__ b2,
               float* __restrict__ out)
{
    extern __shared__ char smem[];
    const int t = blockIdx.x, brow00 = blockIdx.y * (NTILES * BT);
    const int tid = threadIdx.x, wid = tid >> 5, lid = tid & 31;
    const int gid = lid >> 2, tid4 = lid & 3;
    const int pair = wid & 3;           // row group (32 rows)
    const int r0 = pair * 32;
    const int uh = wid >> 2;            // unit half
    const int barid = 1 + pair;

    uint32_t sb;
    asm("{ .reg .u64 tt; cvta.to.shared.u64 tt, %1; cvt.u32.u64 %0, tt; }"
        : "=r"(sb) : "l"(smem));

    // ---- initial stage: X(0) + W0 + W1 + consts ----
    {
        const unsigned char* xp = gX + (size_t)brow00 * XS;
        const unsigned char* w0p = gW0 + (size_t)t * W0T_BYTES;
        const unsigned char* w1p = gW1 + (size_t)t * W1T_BYTES;
        #pragma unroll
        for (int i = tid; i < XT_BYTES / 16; i += NT)
            CP16(sb + SM_X + i * 16, xp + i * 16);
        #pragma unroll
        for (int i = tid; i < W0T_BYTES / 16; i += NT)
            CP16(sb + SM_W0 + i * 16, w0p + i * 16);
        #pragma unroll
        for (int i = tid; i < W1T_BYTES / 16; i += NT)
            CP16(sb + SM_W1 + i * 16, w1p + i * 16);
        asm volatile("cp.async.commit_group;" ::: "memory");
    }
    if (tid < HH) {
        reinterpret_cast<float*>(smem + SM_B0)[tid] = b0[t * HH + tid];
        reinterpret_cast<float*>(smem + SM_B1)[tid] = b1[t * HH + tid];
    }
    if (tid < OO * HH)
        reinterpret_cast<float*>(smem + SM_W2)[tid] = w2[(size_t)t * OO * HH + tid];
    asm volatile("cp.async.wait_group 0;" ::: "memory");
    __syncthreads();

    const float* B0f = reinterpret_cast<const float*>(smem + SM_B0);
    const float* B1f = reinterpret_cast<const float*>(smem + SM_B1);
    const float* W2f = reinterpret_cast<const float*>(smem + SM_W2);
    const float c0 = b2[t * OO], c1 = b2[t * OO + 1];
    char* Hh = smem + SM_X + pair * 8704;   // H aliases this pair's dead X rows

    #pragma unroll 1
    for (int tile = 0; tile < NTILES; tile++) {
        const int brow0 = brow00 + tile * BT;

        // ===================== LAYER 0 (acc init = bias) =====================
        float acc[2][4][4];
        #pragma unroll
        for (int ut = 0; ut < 4; ut++) {
            const int un = uh * 32 + ut * 8 + 2 * tid4;
            const float bA = B0f[un], bB = B0f[un + 1];
            acc[0][ut][0] = bA; acc[0][ut][1] = bB; acc[0][ut][2] = bA; acc[0][ut][3] = bB;
            acc[1][ut][0] = bA; acc[1][ut][1] = bB; acc[1][ut][2] = bA; acc[1][ut][3] = bB;
        }
        {
            const char* XA = smem + SM_X + (r0 + gid) * XS + tid4 * 4;
            const char* WR = smem + SM_W0 + (uh * 32 + gid) * W0S + tid4 * 4;
            #pragma unroll
            for (int ks = 0; ks < 8; ks++) {
                uint32_t xa[2][4];
                #pragma unroll
                for (int rb = 0; rb < 2; rb++) {
                    const char* bp = XA + rb * 16 * XS + ks * 32;
                    xa[rb][0] = *reinterpret_cast<const uint32_t*>(bp);
                    xa[rb][1] = *reinterpret_cast<const uint32_t*>(bp + 8 * XS);
                    xa[rb][2] = *reinterpret_cast<const uint32_t*>(bp + 16);
                    xa[rb][3] = *reinterpret_cast<const uint32_t*>(bp + 8 * XS + 16);
                }
                #pragma unroll
                for (int ut = 0; ut < 4; ut++) {
                    uint32_t bw0 = *reinterpret_cast<const uint32_t*>(WR + ut * 8 * W0S + ks * 32);
                    uint32_t bw1 = *reinterpret_cast<const uint32_t*>(WR + ut * 8 * W0S + ks * 32 + 16);
                    mma_f16(acc[0][ut], xa[0], bw0, bw1);
                    mma_f16(acc[1][ut], xa[1], bw0, bw1);
                }
            }
        }
        asm volatile("bar.sync %0, 64;" :: "r"(barid) : "memory");
        #pragma unroll
        for (int rb = 0; rb < 2; rb++) {
            #pragma unroll
            for (int ut = 0; ut < 4; ut++) {
                const int un = uh * 32 + ut * 8 + 2 * tid4;
                float v0 = acc[rb][ut][0], v1 = acc[rb][ut][1];
                float v2 = acc[rb][ut][2], v3 = acc[rb][ut][3];
                v0 = fmaxf(v0, SLOPE * v0);
                v1 = fmaxf(v1, SLOPE * v1);
                v2 = fmaxf(v2, SLOPE * v2);
                v3 = fmaxf(v3, SLOPE * v3);
                const int ra = (rb * 16 + gid) * HS + un * 2, rbo = ra + 8 * HS;
                *reinterpret_cast<uint32_t*>(Hh + ra)  = packh2(v0, v1);
                *reinterpret_cast<uint32_t*>(Hh + rbo) = packh2(v2, v3);
            }
        }
        asm volatile("bar.sync %0, 64;" :: "r"(barid) : "memory");

        // ===================== LAYER 1 (acc init = bias) =====================
        float h1v[2][4][4];
        #pragma unroll
        for (int ut = 0; ut < 4; ut++) {
            const int un = uh * 32 + ut * 8 + 2 * tid4;
            const float bA = B1f[un], bB = B1f[un + 1];
            h1v[0][ut][0] = bA; h1v[0][ut][1] = bB; h1v[0][ut][2] = bA; h1v[0][ut][3] = bB;
            h1v[1][ut][0] = bA; h1v[1][ut][1] = bB; h1v[1][ut][2] = bA; h1v[1][ut][3] = bB;
        }
        {
            const char* AH = Hh + gid * HS + tid4 * 4;
            const char* WR = smem + SM_W1 + (uh * 32 + gid) * W1S + tid4 * 4;
            #pragma unroll
            for (int ks = 0; ks < 4; ks++) {
                uint32_t ah[2][4];
                #pragma unroll
                for (int rb = 0; rb < 2; rb++) {
                    const char* bp = AH + rb * 16 * HS + ks * 32;
                    ah[rb][0] = *reinterpret_cast<const uint32_t*>(bp);
                    ah[rb][1] = *reinterpret_cast<const uint32_t*>(bp + 8 * HS);
                    ah[rb][2] = *reinterpret_cast<const uint32_t*>(bp + 16);
                    ah[rb][3] = *reinterpret_cast<const uint32_t*>(bp + 8 * HS + 16);
                }
                #pragma unroll
                for (int ut = 0; ut < 4; ut++) {
                    uint32_t bw0 = *reinterpret_cast<const uint32_t*>(WR + ut * 8 * W1S + ks * 32);
                    uint32_t bw1 = *reinterpret_cast<const uint32_t*>(WR + ut * 8 * W1S + ks * 32 + 16);
                    mma_f16(h1v[0][ut], ah[0], bw0, bw1);
                    mma_f16(h1v[1][ut], ah[1], bw0, bw1);
                }
            }
        }
        #pragma unroll
        for (int rb = 0; rb < 2; rb++)
            #pragma unroll
            for (int ut = 0; ut < 4; ut++) {
                h1v[rb][ut][0] = fmaxf(h1v[rb][ut][0], SLOPE * h1v[rb][ut][0]);
                h1v[rb][ut][1] = fmaxf(h1v[rb][ut][1], SLOPE * h1v[rb][ut][1]);
                h1v[rb][ut][2] = fmaxf(h1v[rb][ut][2], SLOPE * h1v[rb][ut][2]);
                h1v[rb][ut][3] = fmaxf(h1v[rb][ut][3], SLOPE * h1v[rb][ut][3]);
            }

        // ===================== LAYER 2 =====================
        {
            float p[2][4];
            #pragma unroll
            for (int rb = 0; rb < 2; rb++) {
                p[rb][0] = p[rb][1] = p[rb][2] = p[rb][3] = 0.f;
                #pragma unroll
                for (int ut = 0; ut < 4; ut++) {
                    const int u = uh * 32 + ut * 8 + 2 * tid4;
                    float2 w2o0 = *reinterpret_cast<const float2*>(W2f + u);
                    float2 w2o1 = *reinterpret_cast<const float2*>(W2f + 64 + u);
                    p[rb][0] += h1v[rb][ut][0] * w2o0.x + h1v[rb][ut][1] * w2o0.y;
                    p[rb][1] += h1v[rb][ut][0] * w2o1.x + h1v[rb][ut][1] * w2o1.y;
                    p[rb][2] += h1v[rb][ut][2] * w2o0.x + h1v[rb][ut][3] * w2o0.y;
                    p[rb][3] += h1v[rb][ut][2] * w2o1.x + h1v[rb][ut][3] * w2o1.y;
                }
                #pragma unroll
                for (int d = 1; d <= 2; d <<= 1) {
                    p[rb][0] += __shfl_xor_sync(0xffffffffu, p[rb][0], d);
                    p[rb][1] += __shfl_xor_sync(0xffffffffu, p[rb][1], d);
                    p[rb][2] += __shfl_xor_sync(0xffffffffu, p[rb][2], d);
                    p[rb][3] += __shfl_xor_sync(0xffffffffu, p[rb][3], d);
                }
            }
            float4* P = reinterpret_cast<float4*>(smem + SM_P);
            if (uh == 1 && tid4 == 0) {
                P[pair * 16 + gid]     = make_float4(p[0][0], p[0][1], p[0][2], p[0][3]);
                P[pair * 16 + 8 + gid] = make_float4(p[1][0], p[1][1], p[1][2], p[1][3]);
            }
            asm volatile("bar.sync %0, 64;" :: "r"(barid) : "memory");
            if (uh == 0 && tid4 == 0) {
                #pragma unroll
                for (int rb = 0; rb < 2; rb++) {
                    float4 q = P[pair * 16 + rb * 8 + gid];
                    const int rowA = brow0 + r0 + rb * 16 + gid, rowB = rowA + 8;
                    out[(size_t)rowA * (DD * OO) + t * OO]     = p[rb][0] + q.x + c0;
                    out[(size_t)rowA * (DD * OO) + t * OO + 1] = p[rb][1] + q.y + c1;
                    out[(size_t)rowB * (DD * OO) + t * OO]     = p[rb][2] + q.z + c0;
                    out[(size_t)rowB * (DD * OO) + t * OO + 1] = p[rb][3] + q.w + c1;
                }
            }
        }

        // ---- refill X with next tile (single buffer; cross-CTA overlap hides it) ----
        if (tile < NTILES - 1) {
            __syncthreads();                    // all reads of X/H done CTA-wide
            const unsigned char* xp = gX + (size_t)(brow00 + (tile + 1) * BT) * XS;
            #pragma unroll
            for (int i = tid; i < XT_BYTES / 16; i += NT)
                CP16(sb + SM_X + i * 16, xp + i * 16);
            asm volatile("cp.async.commit_group;" ::: "memory");
            asm volatile("cp.async.wait_group 0;" ::: "memory");
            __syncthreads();
        }
    }
}

extern "C" void kernel_launch(void* const* d_in, const int* in_sizes, int n_in,
                              void* d_out, int out_size)
{
    const float* x  = (const float*)d_in[0];
    const float* w0 = (const float*)d_in[1];
    const float* w1 = (const float*)d_in[2];
    const float* w2 = (const float*)d_in[3];
    const float* b0 = (const float*)d_in[4];
    const float* b1 = (const float*)d_in[5];
    const float* b2 = (const float*)d_in[6];
    float* out = (float*)d_out;

    const int B = in_sizes[0] / DD;

    cudaFuncSetAttribute(fused_mlp_hmma,
                         cudaFuncAttributeMaxDynamicSharedMemorySize, SMEM_BYTES);

    const int total4 = NX4 + NW04 + NW14;
    prep_kernel<<<(total4 + 255) / 256, 256>>>(x, w0, w1);

    dim3 grid(DD, B / (NTILES * BT));    // (128, 16)
    fused_mlp_hmma<<<grid, NT, SMEM_BYTES>>>(w2, b0, b1, b2, out);
}

// round 17
// speedup vs baseline: 3.4133x; 1.0904x over previous
#include <cuda_runtime.h>
#include <cuda_fp16.h>
#include <cstdint>

// Fused per-variable MLP, mma.sync m16n8k16 fp16 (all fp16 operands, fp32 acc).
// R17: warp tile 32 rows x ALL 64 units. Layer-0 C-fragments ARE layer-1
// A-fragments (packh2 of acc) -> hidden layer never touches smem; no intra-
// tile barriers; layer 2 reduces in-warp. BT=256, 2 tiles/CTA, 2 CTAs/SM.

#define DD 128
#define HH 64
#define OO 2
#define BT 256          // rows per tile (8 warps x 32 rows)
#define NTILES 2
#define NT 256
#define SLOPE 0.01f
#define BATCH 8192

#define XS   272
#define W0S  272
#define W1S  144

#define XT_BYTES  (BT*XS)      // 69632
#define W0T_BYTES (HH*W0S)     // 17408
#define W1T_BYTES (HH*W1S)     // 9216

__device__ __align__(16) unsigned char gX[BATCH*XS];
__device__ __align__(16) unsigned char gW0[DD*W0T_BYTES];
__device__ __align__(16) unsigned char gW1[DD*W1T_BYTES];

// smem byte offsets
#define SM_X   0          // 69632
#define SM_W0  69632      // 17408
#define SM_W1  87040      // 9216
#define SM_B0  96256      // 256
#define SM_B1  96512      // 256
#define SM_W2  96768      // 512
#define SMEM_BYTES 97280

static __device__ __forceinline__ void mma_f16(float acc[4], const uint32_t a[4],
                                               uint32_t b0, uint32_t b1) {
    asm volatile(
        "mma.sync.aligned.m16n8k16.row.col.f32.f16.f16.f32 "
        "{%0,%1,%2,%3}, {%4,%5,%6,%7}, {%8,%9}, {%0,%1,%2,%3};"
        : "+f"(acc[0]), "+f"(acc[1]), "+f"(acc[2]), "+f"(acc[3])
        : "r"(a[0]), "r"(a[1]), "r"(a[2]), "r"(a[3]), "r"(b0), "r"(b1));
}
static __device__ __forceinline__ uint32_t packh2(float a, float b) {
    __half2 h2 = __halves2half2(__float2half_rn(a), __float2half_rn(b));
    return *reinterpret_cast<uint32_t*>(&h2);
}
#define CP16(sdst, gsrc) asm volatile( \
    "cp.async.cg.shared.global [%0], [%1], 16;" :: "r"(sdst), "l"(gsrc))

// ===================== prep =====================
#define NX4  (BATCH*DD/4)
#define NW04 (DD*HH*DD/4)
#define NW14 (DD*HH*HH/4)

__global__ void __launch_bounds__(256)
prep_kernel(const float* __restrict__ x, const float* __restrict__ w0,
            const float* __restrict__ w1)
{
    int idx = blockIdx.x * 256 + threadIdx.x;
    if (idx < NX4) {
        int r = idx >> 5, c = idx & 31;
        float4 v = reinterpret_cast<const float4*>(x)[idx];
        *reinterpret_cast<uint2*>(gX + r * XS + c * 8) =
            make_uint2(packh2(v.x, v.y), packh2(v.z, v.w));
    } else if (idx < NX4 + NW04) {
        int j = idx - NX4;
        int t = j >> 11, k = j & 2047;
        int i = k >> 5, c4 = k & 31;
        float4 v = reinterpret_cast<const float4*>(w0)[j];
        if (c4 == (t >> 2)) reinterpret_cast<float*>(&v)[t & 3] = 0.0f;
        *reinterpret_cast<uint2*>(gW0 + t * W0T_BYTES + i * W0S + c4 * 8) =
            make_uint2(packh2(v.x, v.y), packh2(v.z, v.w));
    } else if (idx < NX4 + NW04 + NW14) {
        int j = idx - NX4 - NW04;
        int t = j >> 10, k = j & 1023;
        int i = k >> 4, c4 = k & 15;
        float4 v = reinterpret_cast<const float4*>(w1)[j];
        *reinterpret_cast<uint2*>(gW1 + t * W1T_BYTES + i * W1S + c4 * 8) =
            make_uint2(packh2(v.x, v.y), packh2(v.z, v.w));
    }
}

// ===================== main =====================
__global__ void __launch_bounds__(NT, 2)
fused_mlp_hmma(const float* __restrict__ w2, const float* __restrict__ b0,
               const float* __restrict__ b1, const float* __restrict__ b2,
               float* __restrict__ out)
{
    extern __shared__ char smem[];
    const int t = blockIdx.x, brow00 = blockIdx.y * (NTILES * BT);
    const int tid = threadIdx.x, wid = tid >> 5, lid = tid & 31;
    const int gid = lid >> 2, tid4 = lid & 3;
    const int r0 = wid * 32;            // this warp's 32 rows (exclusive)

    uint32_t sb;
    asm("{ .reg .u64 tt; cvta.to.shared.u64 tt, %1; cvt.u32.u64 %0, tt; }"
        : "=r"(sb) : "l"(smem));

    // ---- stage X(0) + W0 + W1 + consts ----
    {
        const unsigned char* xp = gX + (size_t)brow00 * XS;
        const unsigned char* w0p = gW0 + (size_t)t * W0T_BYTES;
        const unsigned char* w1p = gW1 + (size_t)t * W1T_BYTES;
        #pragma unroll
        for (int i = tid; i < XT_BYTES / 16; i += NT)
            CP16(sb + SM_X + i * 16, xp + i * 16);
        #pragma unroll
        for (int i = tid; i < W0T_BYTES / 16; i += NT)
            CP16(sb + SM_W0 + i * 16, w0p + i * 16);
        #pragma unroll
        for (int i = tid; i < W1T_BYTES / 16; i += NT)
            CP16(sb + SM_W1 + i * 16, w1p + i * 16);
        asm volatile("cp.async.commit_group;" ::: "memory");
    }
    if (tid < HH) {
        reinterpret_cast<float*>(smem + SM_B0)[tid] = b0[t * HH + tid];
        reinterpret_cast<float*>(smem + SM_B1)[tid] = b1[t * HH + tid];
    }
    if (tid < OO * HH)
        reinterpret_cast<float*>(smem + SM_W2)[tid] = w2[(size_t)t * OO * HH + tid];
    asm volatile("cp.async.wait_group 0;" ::: "memory");
    __syncthreads();

    const float* B0f = reinterpret_cast<const float*>(smem + SM_B0);
    const float* B1f = reinterpret_cast<const float*>(smem + SM_B1);
    const float* W2f = reinterpret_cast<const float*>(smem + SM_W2);
    const float c0 = b2[t * OO], c1 = b2[t * OO + 1];

    #pragma unroll 1
    for (int tile = 0; tile < NTILES; tile++) {
        const int brow0 = brow00 + tile * BT;

        // ===================== LAYER 0 (acc init = bias) =====================
        float acc[2][8][4];
        #pragma unroll
        for (int ut = 0; ut < 8; ut++) {
            const int un = ut * 8 + 2 * tid4;
            const float bA = B0f[un], bB = B0f[un + 1];
            acc[0][ut][0] = bA; acc[0][ut][1] = bB; acc[0][ut][2] = bA; acc[0][ut][3] = bB;
            acc[1][ut][0] = bA; acc[1][ut][1] = bB; acc[1][ut][2] = bA; acc[1][ut][3] = bB;
        }
        {
            const char* XA = smem + SM_X + (r0 + gid) * XS + tid4 * 4;
            const char* WR = smem + SM_W0 + gid * W0S + tid4 * 4;
            #pragma unroll
            for (int ks = 0; ks < 8; ks++) {
                uint32_t xa[2][4];
                #pragma unroll
                for (int rb = 0; rb < 2; rb++) {
                    const char* bp = XA + rb * 16 * XS + ks * 32;
                    xa[rb][0] = *reinterpret_cast<const uint32_t*>(bp);
                    xa[rb][1] = *reinterpret_cast<const uint32_t*>(bp + 8 * XS);
                    xa[rb][2] = *reinterpret_cast<const uint32_t*>(bp + 16);
                    xa[rb][3] = *reinterpret_cast<const uint32_t*>(bp + 8 * XS + 16);
                }
                #pragma unroll
                for (int ut = 0; ut < 8; ut++) {
                    uint32_t bw0 = *reinterpret_cast<const uint32_t*>(WR + ut * 8 * W0S + ks * 32);
                    uint32_t bw1 = *reinterpret_cast<const uint32_t*>(WR + ut * 8 * W0S + ks * 32 + 16);
                    mma_f16(acc[0][ut], xa[0], bw0, bw1);
                    mma_f16(acc[1][ut], xa[1], bw0, bw1);
                }
            }
        }
        // leaky + pack: C-frag of L0 == A-frag of L1 (no smem round-trip)
        uint32_t hpk[2][8][2];
        #pragma unroll
        for (int rb = 0; rb < 2; rb++)
            #pragma unroll
            for (int ut = 0; ut < 8; ut++) {
                float v0 = acc[rb][ut][0], v1 = acc[rb][ut][1];
                float v2 = acc[rb][ut][2], v3 = acc[rb][ut][3];
                v0 = fmaxf(v0, SLOPE * v0);
                v1 = fmaxf(v1, SLOPE * v1);
                v2 = fmaxf(v2, SLOPE * v2);
                v3 = fmaxf(v3, SLOPE * v3);
                hpk[rb][ut][0] = packh2(v0, v1);   // (row gid,  k un..un+1)
                hpk[rb][ut][1] = packh2(v2, v3);   // (row gid+8, k un..un+1)
            }

        // ===================== LAYER 1 (A from registers) =====================
        float h1v[2][8][4];
        #pragma unroll
        for (int ut = 0; ut < 8; ut++) {
            const int un = ut * 8 + 2 * tid4;
            const float bA = B1f[un], bB = B1f[un + 1];
            h1v[0][ut][0] = bA; h1v[0][ut][1] = bB; h1v[0][ut][2] = bA; h1v[0][ut][3] = bB;
            h1v[1][ut][0] = bA; h1v[1][ut][1] = bB; h1v[1][ut][2] = bA; h1v[1][ut][3] = bB;
        }
        {
            const char* WR = smem + SM_W1 + gid * W1S + tid4 * 4;
            #pragma unroll
            for (int ks = 0; ks < 4; ks++) {
                uint32_t ah[2][4];
                #pragma unroll
                for (int rb = 0; rb < 2; rb++) {
                    ah[rb][0] = hpk[rb][2 * ks][0];
                    ah[rb][1] = hpk[rb][2 * ks][1];
                    ah[rb][2] = hpk[rb][2 * ks + 1][0];
                    ah[rb][3] = hpk[rb][2 * ks + 1][1];
                }
                #pragma unroll
                for (int ut = 0; ut < 8; ut++) {
                    uint32_t bw0 = *reinterpret_cast<const uint32_t*>(WR + ut * 8 * W1S + ks * 32);
                    uint32_t bw1 = *reinterpret_cast<const uint32_t*>(WR + ut * 8 * W1S + ks * 32 + 16);
                    mma_f16(h1v[0][ut], ah[0], bw0, bw1);
                    mma_f16(h1v[1][ut], ah[1], bw0, bw1);
                }
            }
        }
        #pragma unroll
        for (int rb = 0; rb < 2; rb++)
            #pragma unroll
            for (int ut = 0; ut < 8; ut++) {
                h1v[rb][ut][0] = fmaxf(h1v[rb][ut][0], SLOPE * h1v[rb][ut][0]);
                h1v[rb][ut][1] = fmaxf(h1v[rb][ut][1], SLOPE * h1v[rb][ut][1]);
                h1v[rb][ut][2] = fmaxf(h1v[rb][ut][2], SLOPE * h1v[rb][ut][2]);
                h1v[rb][ut][3] = fmaxf(h1v[rb][ut][3], SLOPE * h1v[rb][ut][3]);
            }

        // ===================== LAYER 2 (in-warp reduce) =====================
        #pragma unroll
        for (int rb = 0; rb < 2; rb++) {
            float p0 = 0.f, p1 = 0.f, p2 = 0.f, p3 = 0.f;
            #pragma unroll
            for (int ut = 0; ut < 8; ut++) {
                const int u = ut * 8 + 2 * tid4;
                float2 w2o0 = *reinterpret_cast<const float2*>(W2f + u);
                float2 w2o1 = *reinterpret_cast<const float2*>(W2f + 64 + u);
                p0 += h1v[rb][ut][0] * w2o0.x + h1v[rb][ut][1] * w2o0.y;   // row gid,  o0
                p1 += h1v[rb][ut][0] * w2o1.x + h1v[rb][ut][1] * w2o1.y;   // row gid,  o1
                p2 += h1v[rb][ut][2] * w2o0.x + h1v[rb][ut][3] * w2o0.y;   // row gid+8,o0
                p3 += h1v[rb][ut][2] * w2o1.x + h1v[rb][ut][3] * w2o1.y;   // row gid+8,o1
            }
            #pragma unroll
            for (int d = 1; d <= 2; d <<= 1) {
                p0 += __shfl_xor_sync(0xffffffffu, p0, d);
                p1 += __shfl_xor_sync(0xffffffffu, p1, d);
                p2 += __shfl_xor_sync(0xffffffffu, p2, d);
                p3 += __shfl_xor_sync(0xffffffffu, p3, d);
            }
            if (tid4 == 0) {
                const int rowA = brow0 + r0 + rb * 16 + gid, rowB = rowA + 8;
                out[(size_t)rowA * (DD * OO) + t * OO]     = p0 + c0;
                out[(size_t)rowA * (DD * OO) + t * OO + 1] = p1 + c1;
                out[(size_t)rowB * (DD * OO) + t * OO]     = p2 + c0;
                out[(size_t)rowB * (DD * OO) + t * OO + 1] = p3 + c1;
            }
        }

        // ---- refill X with next tile ----
        if (tile < NTILES - 1) {
            __syncthreads();                    // all warps done reading X
            const unsigned char* xp = gX + (size_t)(brow00 + (tile + 1) * BT) * XS;
            #pragma unroll
            for (int i = tid; i < XT_BYTES / 16; i += NT)
                CP16(sb + SM_X + i * 16, xp + i * 16);
            asm volatile("cp.async.commit_group;" ::: "memory");
            asm volatile("cp.async.wait_group 0;" ::: "memory");
            __syncthreads();
        }
    }
}

extern "C" void kernel_launch(void* const* d_in, const int* in_sizes, int n_in,
                              void* d_out, int out_size)
{
    const float* x  = (const float*)d_in[0];
    const float* w0 = (const float*)d_in[1];
    const float* w1 = (const float*)d_in[2];
    const float* w2 = (const float*)d_in[3];
    const float* b0 = (const float*)d_in[4];
    const float* b1 = (const float*)d_in[5];
    const float* b2 = (const float*)d_in[6];
    float* out = (float*)d_out;

    const int B = in_sizes[0] / DD;

    cudaFuncSetAttribute(fused_mlp_hmma,
                         cudaFuncAttributeMaxDynamicSharedMemorySize, SMEM_BYTES);

    const int total4 = NX4 + NW04 + NW14;
    prep_kernel<<<(total4 + 255) / 256, 256>>>(x, w0, w1);

    dim3 grid(DD, B / (NTILES * BT));    // (128, 16)
    fused_mlp_hmma<<<grid, NT, SMEM_BYTES>>>(w2, b0, b1, b2, out);
}